// round 3
// baseline (speedup 1.0000x reference)
#include <cuda_runtime.h>
#include <cuda_bf16.h>

#define Bb 8
#define Nn 96
#define Dd 256
#define Hh 8
#define CUTOFF 5.0f
#define PI_F 3.14159265358979f

typedef unsigned long long u64;

// ---------------- scratch (device globals; no allocation allowed) ----------------
__device__ float gQ[Bb*Nn*Dd];
__device__ float gK[Bb*Nn*Dd];
__device__ float gV[Bb*Nn*Dd];
__device__ float gDU[Bb*Nn*3*Dd];
__device__ float gWS[Bb*Nn*3*Dd];
__device__ float gWT[Bb*Nn*3*Dd];
__device__ unsigned char gMask[Bb*Nn*Nn];

// ---------------- packed f32x2 helpers (Blackwell FFMA2: 2x fp32 throughput) ----
__device__ __forceinline__ u64 pack2(float x) {
    u64 d;
    asm("mov.b64 %0, {%1, %1};" : "=l"(d) : "f"(x));
    return d;
}
__device__ __forceinline__ void ffma2(u64& acc, u64 a, u64 b) {
    asm("fma.rn.f32x2 %0, %1, %2, %0;" : "+l"(acc) : "l"(a), "l"(b));
}
__device__ __forceinline__ float2 unpack2(u64 v) {
    float lo, hi;
    asm("mov.b64 {%0, %1}, %2;" : "=f"(lo), "=f"(hi) : "l"(v));
    return make_float2(lo, hi);
}

// ---------------- mask dtype canonicalization ----------------
__global__ void mask_conv_kernel(const unsigned char* __restrict__ raw) {
    __shared__ int mode_s;
    int tid = threadIdx.x;
    if (tid == 0) mode_s = 0;
    __syncthreads();
    int local = 0;
    const int NEL = Bb*Nn*Nn;
    for (int i = tid; i < NEL; i += 256) {
        unsigned char bch = raw[i];
        if (bch != 0 && (i & 3) != 0) {
            if (bch == 0x80 || bch == 0x3F) local |= 2;   // float32 pattern
            else                            local |= 1;   // byte-per-element
        }
    }
    if (local) atomicOr(&mode_s, local);
    __syncthreads();
    int mode = mode_s;
    for (int i = tid; i < NEL; i += 256) {
        unsigned char v;
        if (mode & 1)      v = (raw[i] != 0);
        else if (mode & 2) v = (((const float*)raw)[i] != 0.0f);
        else               v = (((const int*)raw)[i]   != 0);
        gMask[i] = v;
    }
}

// ---------------- FMA-only silu ----------------
__device__ __forceinline__ float fast_silu(float x) {
    float t = x * -1.4426950408889634f;
    t = fminf(fmaxf(t, -30.0f), 30.0f);
    float fn = rintf(t);
    float f  = t - fn;
    float p = 1.3333558e-3f;
    p = fmaf(p, f, 9.6181291e-3f);
    p = fmaf(p, f, 5.5504109e-2f);
    p = fmaf(p, f, 2.4022651e-1f);
    p = fmaf(p, f, 6.9314718e-1f);
    p = fmaf(p, f, 1.0f);
    int ei = (int)fn;
    float sc = __int_as_float((ei + 127) << 23);
    float e = p * sc;
    float d = 1.0f + e;
    float y = __int_as_float(0x7EF311C3u - __float_as_int(d));
    y = y * (2.0f - d * y);
    y = y * (2.0f - d * y);
    y = y * (2.0f - d * y);
    return x * y;
}

// ---------------- K0: Q/K/V = x @ W + b ----------------
__global__ __launch_bounds__(256) void qkv_kernel(
    const float* __restrict__ x,
    const float* __restrict__ Wq, const float* __restrict__ bq,
    const float* __restrict__ Wk, const float* __restrict__ bk,
    const float* __restrict__ Wv, const float* __restrict__ bv)
{
    __shared__ float xs[12][256];
    __shared__ float wch[32][256];
    int tid = threadIdx.x;
    int b   = blockIdx.x >> 3;
    int rg  = blockIdx.x & 7;
    int row0 = rg * 12;

    #pragma unroll
    for (int i = 0; i < 12; ++i)
        xs[i][tid] = x[(b*Nn + row0 + i)*Dd + tid];

    const float* Ws[3]  = {Wq, Wk, Wv};
    const float* bs[3]  = {bq, bk, bv};
    float*       os[3]  = {gQ, gK, gV};

    for (int w = 0; w < 3; ++w) {
        float acc[12];
        #pragma unroll
        for (int i = 0; i < 12; ++i) acc[i] = 0.f;
        const float* W = Ws[w];
        for (int ks = 0; ks < 8; ++ks) {
            __syncthreads();
            #pragma unroll
            for (int i = 0; i < 32; ++i)
                wch[i][tid] = W[(ks*32 + i)*Dd + tid];
            __syncthreads();
            #pragma unroll
            for (int kk = 0; kk < 32; kk += 4) {
                float w0 = wch[kk+0][tid], w1 = wch[kk+1][tid];
                float w2 = wch[kk+2][tid], w3 = wch[kk+3][tid];
                #pragma unroll
                for (int r = 0; r < 12; ++r) {
                    float4 xv = *(const float4*)&xs[r][ks*32 + kk];
                    acc[r] = fmaf(xv.x, w0, acc[r]);
                    acc[r] = fmaf(xv.y, w1, acc[r]);
                    acc[r] = fmaf(xv.z, w2, acc[r]);
                    acc[r] = fmaf(xv.w, w3, acc[r]);
                }
            }
        }
        float bias = bs[w][tid];
        #pragma unroll
        for (int r = 0; r < 12; ++r)
            os[w][(b*Nn + row0 + r)*Dd + tid] = acc[r] + bias;
        __syncthreads();
    }
}

// ---------------- shared GEMM tile (512 threads, FFMA2) ----------------
// out rows: warp r (0..15) owns m = r + 16*i, i<6. cols: lane g owns 4 cols
// (as 2 packed f32x2 pairs) in the 128-wide chunk starting at cc.
__device__ __forceinline__ void gemm_tile2(
    const float* __restrict__ src,   // smem [96][256]
    const float* __restrict__ Wglob, // global [256][256]
    int cc, float* wch, int g, int r, int tid, u64 acc2[6][2])
{
    for (int ks = 0; ks < 8; ++ks) {
        __syncthreads();
        {
            const float* Wp = Wglob + (ks*32)*Dd + cc;
            float4* w4 = (float4*)wch;
            #pragma unroll
            for (int i = 0; i < 2; ++i) {
                int lin = tid + 512*i;          // 0..1023 float4s = 32x128 floats
                int row = lin >> 5;
                int c4  = lin & 31;
                w4[lin] = *(const float4*)(Wp + row*Dd + c4*4);
            }
        }
        __syncthreads();
        #pragma unroll
        for (int kk = 0; kk < 32; kk += 4) {
            u64 wa0 = *(const u64*)&wch[(kk+0)*128 + g*4];
            u64 wb0 = *(const u64*)&wch[(kk+0)*128 + g*4 + 2];
            u64 wa1 = *(const u64*)&wch[(kk+1)*128 + g*4];
            u64 wb1 = *(const u64*)&wch[(kk+1)*128 + g*4 + 2];
            u64 wa2 = *(const u64*)&wch[(kk+2)*128 + g*4];
            u64 wb2 = *(const u64*)&wch[(kk+2)*128 + g*4 + 2];
            u64 wa3 = *(const u64*)&wch[(kk+3)*128 + g*4];
            u64 wb3 = *(const u64*)&wch[(kk+3)*128 + g*4 + 2];
            #pragma unroll
            for (int i = 0; i < 6; ++i) {
                float4 e = *(const float4*)&src[(r + (i<<4))*Dd + ks*32 + kk];
                u64 ex = pack2(e.x), ey = pack2(e.y), ez = pack2(e.z), ew = pack2(e.w);
                ffma2(acc2[i][0], ex, wa0); ffma2(acc2[i][1], ex, wb0);
                ffma2(acc2[i][0], ey, wa1); ffma2(acc2[i][1], ey, wb1);
                ffma2(acc2[i][0], ez, wa2); ffma2(acc2[i][1], ez, wb2);
                ffma2(acc2[i][0], ew, wa3); ffma2(acc2[i][1], ew, wb3);
            }
        }
    }
}

// ---------------- K1: fused dk-GEMM + attention + attn_per_nodes + du-GEMM ----------------
#define FUSED_SMEM_FLOATS (24576 + 24576 + 4096 + 256 + 96 + 96 + 288 + 256 + 768)

__global__ __launch_bounds__(512, 1) void fused_kernel(
    const float* __restrict__ edge,
    const float* __restrict__ dist,
    const float* __restrict__ vec,
    const float* __restrict__ Wdk, const float* __restrict__ bdk,
    const float* __restrict__ Wdu, const float* __restrict__ bdu,
    float* __restrict__ out_attn)
{
    extern __shared__ float sm[];
    float* Es     = sm;                 // 96x256 edge tile
    float* As     = Es + 24576;         // 96x256 attn_per_nodes
    float* wch    = As + 24576;         // 32x128 weight slice
    float* qs     = wch + 4096;         // 256
    float* scl    = qs + 256;           // 96
    float* mk     = scl + 96;           // 96
    float* vecs   = mk + 96;            // 96x3
    float* bias_s = vecs + 288;         // 256 (bdk then bdu)
    float* du_s   = bias_s + 256;       // 3x256

    int tid = threadIdx.x;
    int b = blockIdx.x / Nn;
    int n = blockIdx.x % Nn;
    int g = tid & 31;
    int r = tid >> 5;                   // 0..15
    size_t ebase = (size_t)(b*Nn + n) * Nn * Dd;

    // ------- loads -------
    {
        const float4* e4  = (const float4*)(edge + ebase);
        float4*       Es4 = (float4*)Es;
        #pragma unroll
        for (int i = 0; i < 12; ++i) Es4[tid + 512*i] = e4[tid + 512*i];
    }
    if (tid < 256) {
        qs[tid]     = gQ[(b*Nn + n)*Dd + tid];
        bias_s[tid] = bdk[tid];
        du_s[tid] = 0.f; du_s[tid+256] = 0.f; du_s[tid+512] = 0.f;
    }
    if (tid < 96) {
        int m = tid;
        unsigned char mm = gMask[(b*Nn + n)*Nn + m];
        float dd = dist[(b*Nn + n)*Nn + m];
        float cs = (dd < CUTOFF) ? 0.5f*(cosf(dd*(PI_F/CUTOFF)) + 1.f) : 0.f;
        scl[m] = mm ? 0.f : cs;
        mk[m]  = mm ? 0.f : 1.f;
    }
    if (tid < 288) {
        size_t vbase = (size_t)(b*Nn + n) * Nn * 3;
        vecs[tid] = vec[vbase + tid];
    }
    __syncthreads();

    // ------- GEMM1: dk = silu(E @ Wdk + bdk); attn weights; attn_per_nodes -> As -------
    #pragma unroll 1
    for (int cc = 0; cc < 256; cc += 128) {
        u64 acc2[6][2];
        #pragma unroll
        for (int i = 0; i < 6; ++i) { acc2[i][0] = 0ull; acc2[i][1] = 0ull; }
        gemm_tile2(Es, Wdk, cc, wch, g, r, tid, acc2);

        int col0 = cc + g*4;
        float4 qv = *(const float4*)&qs[col0];
        float4 bb = *(const float4*)&bias_s[col0];
        #pragma unroll
        for (int i = 0; i < 6; ++i) {
            int m = r + (i << 4);
            float2 p0 = unpack2(acc2[i][0]);
            float2 p1 = unpack2(acc2[i][1]);
            float4 kv = *(const float4*)&gK[(b*Nn + m)*Dd + col0];
            float p;
            p  = fast_silu(p0.x + bb.x) * qv.x * kv.x;
            p += fast_silu(p0.y + bb.y) * qv.y * kv.y;
            p += fast_silu(p1.x + bb.z) * qv.z * kv.z;
            p += fast_silu(p1.y + bb.w) * qv.w * kv.w;
            // reduce one head's 32 dims: 8 adjacent lanes x 4 cols
            p += __shfl_xor_sync(0xffffffffu, p, 1);
            p += __shfl_xor_sync(0xffffffffu, p, 2);
            p += __shfl_xor_sync(0xffffffffu, p, 4);
            float prob = fast_silu(p) * scl[m];
            float4 vv = *(const float4*)&gV[(b*Nn + m)*Dd + col0];
            float4 a;
            a.x = prob*vv.x; a.y = prob*vv.y; a.z = prob*vv.z; a.w = prob*vv.w;
            *(float4*)&As[m*Dd + col0] = a;
        }
    }
    __syncthreads();

    // ------- attn = sum_m As[m][:]; swap bias to bdu -------
    if (tid < 256) {
        float s = 0.f;
        #pragma unroll
        for (int m = 0; m < 96; ++m) s += As[m*Dd + tid];
        out_attn[(b*Nn + n)*Dd + tid] = s;
        bias_s[tid] = bdu[tid];
    }

    // ------- GEMM2: du_in = As @ Wdu + bdu (masked); du += du_in * vec -------
    #pragma unroll 1
    for (int cc = 0; cc < 256; cc += 128) {
        u64 acc2[6][2];
        #pragma unroll
        for (int i = 0; i < 6; ++i) { acc2[i][0] = 0ull; acc2[i][1] = 0ull; }
        gemm_tile2(As, Wdu, cc, wch, g, r, tid, acc2);

        int col0 = cc + g*4;
        float4 bb = *(const float4*)&bias_s[col0];
        float bbv[4] = {bb.x, bb.y, bb.z, bb.w};
        float dup0[4] = {0,0,0,0}, dup1[4] = {0,0,0,0}, dup2[4] = {0,0,0,0};
        #pragma unroll
        for (int i = 0; i < 6; ++i) {
            int m = r + (i << 4);
            float keep = mk[m];
            float vc0 = vecs[m*3+0], vc1 = vecs[m*3+1], vc2 = vecs[m*3+2];
            float2 p0 = unpack2(acc2[i][0]);
            float2 p1 = unpack2(acc2[i][1]);
            float av[4] = {p0.x, p0.y, p1.x, p1.y};
            #pragma unroll
            for (int j = 0; j < 4; ++j) {
                float din = (av[j] + bbv[j]) * keep;
                dup0[j] = fmaf(din, vc0, dup0[j]);
                dup1[j] = fmaf(din, vc1, dup1[j]);
                dup2[j] = fmaf(din, vc2, dup2[j]);
            }
        }
        #pragma unroll
        for (int j = 0; j < 4; ++j) {
            atomicAdd(&du_s[0*Dd + col0 + j], dup0[j]);
            atomicAdd(&du_s[1*Dd + col0 + j], dup1[j]);
            atomicAdd(&du_s[2*Dd + col0 + j], dup2[j]);
        }
    }
    __syncthreads();

    if (tid < 256) {
        #pragma unroll
        for (int c = 0; c < 3; ++c)
            gDU[((b*Nn + n)*3 + c)*Dd + tid] = du_s[c*Dd + tid];
    }
}

// ---------------- K2: w = du @ Wdih; split into ws / wt ----------------
__global__ __launch_bounds__(256) void w_kernel(const float* __restrict__ Wdih)
{
    __shared__ float dus[12*256];
    __shared__ float wch[16][512];
    int tid = threadIdx.x;
    int b  = blockIdx.x / 24;
    int ng = blockIdx.x % 24;
    int nbase = ng * 4;

    size_t dbase = (size_t)(b*Nn + nbase) * 3 * Dd;
    #pragma unroll
    for (int i = 0; i < 12; ++i)
        dus[tid + 256*i] = gDU[dbase + tid + 256*i];

    float acc0[12], acc1[12];
    #pragma unroll
    for (int q = 0; q < 12; ++q) { acc0[q] = 0.f; acc1[q] = 0.f; }

    for (int ks = 0; ks < 16; ++ks) {
        __syncthreads();
        #pragma unroll
        for (int i = 0; i < 32; ++i) {
            int lin = tid + 256*i;
            int row = lin >> 9;
            int col = lin & 511;
            wch[row][col] = Wdih[(ks*16 + row)*512 + col];
        }
        __syncthreads();
        #pragma unroll
        for (int kk = 0; kk < 16; ++kk) {
            float w0 = wch[kk][tid];
            float w1 = wch[kk][tid + 256];
            #pragma unroll
            for (int q = 0; q < 12; ++q) {
                float xv = dus[q*256 + ks*16 + kk];
                acc0[q] = fmaf(xv, w0, acc0[q]);
                acc1[q] = fmaf(xv, w1, acc1[q]);
            }
        }
    }
    #pragma unroll
    for (int q = 0; q < 12; ++q) {
        int ni = q / 3, c = q % 3;
        gWS[((b*Nn + nbase + ni)*3 + c)*Dd + tid] = acc0[q];
        gWT[((b*Nn + nbase + ni)*3 + c)*Dd + tid] = acc1[q];
    }
}

// ---------------- K3: ipe = silu(E @ Wea + bea) * sum_c ws[n,c,:]*wt[m,c,:] ----------------
#define IPE_SMEM_FLOATS (24576 + 4096 + 768 + 256)

__global__ __launch_bounds__(512, 1) void ipe_kernel(
    const float* __restrict__ edge,
    const float* __restrict__ Wea, const float* __restrict__ bea,
    float* __restrict__ out_ipe)
{
    extern __shared__ float sm[];
    float* Es    = sm;            // 96x256
    float* wch   = Es + 24576;    // 32x128
    float* wsr   = wch + 4096;    // 3x256
    float* bea_s = wsr + 768;     // 256

    int tid = threadIdx.x;
    int b = blockIdx.x / Nn;
    int n = blockIdx.x % Nn;
    int g = tid & 31;
    int r = tid >> 5;             // 0..15
    size_t ebase = (size_t)(b*Nn + n) * Nn * Dd;

    {
        const float4* e4  = (const float4*)(edge + ebase);
        float4*       Es4 = (float4*)Es;
        #pragma unroll
        for (int i = 0; i < 12; ++i) Es4[tid + 512*i] = e4[tid + 512*i];
    }
    if (tid < 256) {
        bea_s[tid] = bea[tid];
        size_t wbase = (size_t)(b*Nn + n) * 3 * Dd;
        #pragma unroll
        for (int i = 0; i < 3; ++i) wsr[tid + 256*i] = gWS[wbase + tid + 256*i];
    }
    __syncthreads();

    #pragma unroll 1
    for (int cc = 0; cc < 256; cc += 128) {
        u64 acc2[6][2];
        #pragma unroll
        for (int i = 0; i < 6; ++i) { acc2[i][0] = 0ull; acc2[i][1] = 0ull; }
        gemm_tile2(Es, Wea, cc, wch, g, r, tid, acc2);

        int col0 = cc + g*4;
        float4 bb = *(const float4*)&bea_s[col0];
        float4 w0 = *(const float4*)&wsr[0*Dd + col0];
        float4 w1 = *(const float4*)&wsr[1*Dd + col0];
        float4 w2 = *(const float4*)&wsr[2*Dd + col0];
        #pragma unroll
        for (int i = 0; i < 6; ++i) {
            int m = r + (i << 4);
            float2 p0 = unpack2(acc2[i][0]);
            float2 p1 = unpack2(acc2[i][1]);
            const float* wtb = &gWT[((b*Nn + m)*3)*Dd + col0];
            float4 t0 = *(const float4*)(wtb);
            float4 t1 = *(const float4*)(wtb + 256);
            float4 t2 = *(const float4*)(wtb + 512);
            float4 o;
            o.x = fast_silu(p0.x + bb.x) * (w0.x*t0.x + w1.x*t1.x + w2.x*t2.x);
            o.y = fast_silu(p0.y + bb.y) * (w0.y*t0.y + w1.y*t1.y + w2.y*t2.y);
            o.z = fast_silu(p1.x + bb.z) * (w0.z*t0.z + w1.z*t1.z + w2.z*t2.z);
            o.w = fast_silu(p1.y + bb.w) * (w0.w*t0.w + w1.w*t1.w + w2.w*t2.w);
            *(float4*)&out_ipe[((size_t)(b*Nn + n)*Nn + m)*Dd + col0] = o;
        }
    }
}

// ---------------- launch ----------------
extern "C" void kernel_launch(void* const* d_in, const int* in_sizes, int n_in,
                              void* d_out, int out_size)
{
    const float* x    = (const float*)d_in[0];
    const float* vec  = (const float*)d_in[1];
    const float* dist = (const float*)d_in[2];
    const float* edge = (const float*)d_in[3];
    const unsigned char* mraw = (const unsigned char*)d_in[4];
    const float* Wq   = (const float*)d_in[5];
    const float* bq   = (const float*)d_in[6];
    const float* Wk   = (const float*)d_in[7];
    const float* bk   = (const float*)d_in[8];
    const float* Wv   = (const float*)d_in[9];
    const float* bv   = (const float*)d_in[10];
    const float* Wdk  = (const float*)d_in[11];
    const float* bdk  = (const float*)d_in[12];
    const float* Wdu  = (const float*)d_in[13];
    const float* bdu  = (const float*)d_in[14];
    const float* Wdih = (const float*)d_in[15];
    const float* Wea  = (const float*)d_in[16];
    const float* bea  = (const float*)d_in[17];

    float* out_attn = (float*)d_out;                    // (B,N,D)
    float* out_ipe  = out_attn + Bb*Nn*Dd;              // (B,N,N,D)

    cudaFuncSetAttribute(fused_kernel, cudaFuncAttributeMaxDynamicSharedMemorySize,
                         FUSED_SMEM_FLOATS * (int)sizeof(float));
    cudaFuncSetAttribute(ipe_kernel, cudaFuncAttributeMaxDynamicSharedMemorySize,
                         IPE_SMEM_FLOATS * (int)sizeof(float));

    mask_conv_kernel<<<1, 256>>>(mraw);
    qkv_kernel<<<64, 256>>>(x, Wq, bq, Wk, bk, Wv, bv);
    fused_kernel<<<Bb*Nn, 512, FUSED_SMEM_FLOATS * sizeof(float)>>>(
        edge, dist, vec, Wdk, bdk, Wdu, bdu, out_attn);
    w_kernel<<<Bb*24, 256>>>(Wdih);
    ipe_kernel<<<Bb*Nn, 512, IPE_SMEM_FLOATS * sizeof(float)>>>(
        edge, Wea, bea, out_ipe);
}

// round 7
// speedup vs baseline: 2.1004x; 2.1004x over previous
#include <cuda_runtime.h>
#include <cuda_bf16.h>
#include <cstdint>

#define Bb 8
#define Nn 96
#define Dd 256
#define CUTOFF 5.0f
#define PI_F 3.14159265358979f

// ================= scratch (device globals; no allocation allowed) =============
__device__ float gQ[Bb*Nn*Dd];
__device__ float gK[Bb*Nn*Dd];
__device__ float gV[Bb*Nn*Dd];
__device__ float gDU[Bb*Nn*3*Dd];
__device__ float gWS[Bb*Nn*3*Dd];
__device__ float gWT[Bb*Nn*3*Dd];
__device__ unsigned char gMask[Bb*Nn*Nn];
// Pre-converted weights: [mat: dk,du,ea][prec: hi,lo][k-slice 0..3][32KB swizzled B tile]
// B tile per slice: [256 n][64 k] bf16, 8x64 atoms, XOR-swizzled (ldmatrix .col operand).
__device__ __align__(16) unsigned char gWB[3][2][4][32768];

// ================= helpers =================
__device__ __forceinline__ uint32_t smem_u32(const void* p) {
    uint32_t a;
    asm("{ .reg .u64 t; cvta.to.shared.u64 t, %1; cvt.u32.u64 %0, t; }" : "=r"(a) : "l"(p));
    return a;
}
__device__ __forceinline__ uint32_t swz(uint32_t b) { return b ^ ((b >> 3) & 0x70); }

// B slice byte offset: [256 n][64 k] bf16, atom = 8 n-rows x 128B
__device__ __forceinline__ uint32_t b_off(int n, int k) {
    uint32_t byte = ((n >> 3) << 10) + ((n & 7) << 7) + (k << 1);
    return swz(byte);
}
// A tile byte offset: [96 rows][256 cols] bf16, atoms 8r x 64c, 12 atom-rows per atom-col
__device__ __forceinline__ uint32_t a2_off(int row, int col) {
    uint32_t byte = (uint32_t)(((col >> 6) * 12 + (row >> 3)) << 10) + ((row & 7) << 7) + ((col & 63) << 1);
    return swz(byte);
}

__device__ __forceinline__ unsigned pack_bf2(float a, float b) {
    __nv_bfloat162 h = __floats2bfloat162_rn(a, b);
    return *reinterpret_cast<unsigned*>(&h);
}
__device__ __forceinline__ void split_bf(float x, float& hi, float& lo) {
    __nv_bfloat16 h = __float2bfloat16_rn(x);
    hi = __bfloat162float(h);
    lo = x - hi;
}

__device__ __forceinline__ void ldsm_x4(uint32_t& r0, uint32_t& r1, uint32_t& r2, uint32_t& r3, uint32_t addr) {
    asm volatile("ldmatrix.sync.aligned.m8n8.x4.shared.b16 {%0,%1,%2,%3}, [%4];"
                 : "=r"(r0), "=r"(r1), "=r"(r2), "=r"(r3) : "r"(addr));
}
__device__ __forceinline__ void ldsm_x2(uint32_t& r0, uint32_t& r1, uint32_t addr) {
    asm volatile("ldmatrix.sync.aligned.m8n8.x2.shared.b16 {%0,%1}, [%2];"
                 : "=r"(r0), "=r"(r1) : "r"(addr));
}
__device__ __forceinline__ void mma16816(float* c, uint32_t a0, uint32_t a1, uint32_t a2, uint32_t a3,
                                         uint32_t b0, uint32_t b1) {
    asm volatile("mma.sync.aligned.m16n8k16.row.col.f32.bf16.bf16.f32 "
                 "{%0,%1,%2,%3}, {%4,%5,%6,%7}, {%8,%9}, {%0,%1,%2,%3};"
                 : "+f"(c[0]), "+f"(c[1]), "+f"(c[2]), "+f"(c[3])
                 : "r"(a0), "r"(a1), "r"(a2), "r"(a3), "r"(b0), "r"(b1));
}

// ================= FMA-only silu =================
__device__ __forceinline__ float fast_silu(float x) {
    float t = x * -1.4426950408889634f;
    t = fminf(fmaxf(t, -30.0f), 30.0f);
    float fn = rintf(t);
    float f  = t - fn;
    float p = 1.3333558e-3f;
    p = fmaf(p, f, 9.6181291e-3f);
    p = fmaf(p, f, 5.5504109e-2f);
    p = fmaf(p, f, 2.4022651e-1f);
    p = fmaf(p, f, 6.9314718e-1f);
    p = fmaf(p, f, 1.0f);
    float sc = __int_as_float(((int)fn + 127) << 23);
    float e = p * sc;
    float d = 1.0f + e;
    float y = __int_as_float(0x7EF311C3u - __float_as_int(d));
    y = y * (2.0f - d * y);
    y = y * (2.0f - d * y);
    y = y * (2.0f - d * y);
    return x * y;
}

// ================= mask dtype canonicalization =================
__global__ void mask_conv_kernel(const unsigned char* __restrict__ raw) {
    __shared__ int mode_s;
    int tid = threadIdx.x;
    if (tid == 0) mode_s = 0;
    __syncthreads();
    int local = 0;
    const int NEL = Bb*Nn*Nn;
    for (int i = tid; i < NEL; i += 256) {
        unsigned char bch = raw[i];
        if (bch != 0 && (i & 3) != 0) {
            if (bch == 0x80 || bch == 0x3F) local |= 2;
            else                            local |= 1;
        }
    }
    if (local) atomicOr(&mode_s, local);
    __syncthreads();
    int mode = mode_s;
    for (int i = tid; i < NEL; i += 256) {
        unsigned char v;
        if (mode & 1)      v = (raw[i] != 0);
        else if (mode & 2) v = (((const float*)raw)[i] != 0.0f);
        else               v = (((const int*)raw)[i]   != 0);
        gMask[i] = v;
    }
}

// ================= W pre-convert: W[k][n] fp32 -> bf16 hi/lo slices [n][k], pre-swizzled ====
__global__ __launch_bounds__(256) void wconv_kernel(
    const float* __restrict__ Wdk, const float* __restrict__ Wdu, const float* __restrict__ Wea)
{
    int idx = blockIdx.x * 256 + threadIdx.x;      // 3*256*128
    int mat = idx / (256*128);
    int rem = idx % (256*128);
    int n   = rem / 128;
    int kp  = rem % 128;
    int k0  = kp * 2;
    const float* W = (mat == 0) ? Wdk : (mat == 1) ? Wdu : Wea;
    float w0 = W[k0*Dd + n];
    float w1 = W[(k0+1)*Dd + n];
    float h0, l0, h1, l1;
    split_bf(w0, h0, l0);
    split_bf(w1, h1, l1);
    int slice = k0 >> 6;
    int kk = k0 & 63;
    uint32_t off = b_off(n, kk);
    *(unsigned*)(&gWB[mat][0][slice][off]) = pack_bf2(h0, h1);
    *(unsigned*)(&gWB[mat][1][slice][off]) = pack_bf2(l0, l1);
}

// ================= K0: Q/K/V = x @ W + b (SIMT, small) =================
__global__ __launch_bounds__(256) void qkv_kernel(
    const float* __restrict__ x,
    const float* __restrict__ Wq, const float* __restrict__ bq,
    const float* __restrict__ Wk, const float* __restrict__ bk,
    const float* __restrict__ Wv, const float* __restrict__ bv)
{
    __shared__ float xs[12][256];
    __shared__ float wch[32][256];
    int tid = threadIdx.x;
    int b   = blockIdx.x >> 3;
    int rg  = blockIdx.x & 7;
    int row0 = rg * 12;

    #pragma unroll
    for (int i = 0; i < 12; ++i)
        xs[i][tid] = x[(b*Nn + row0 + i)*Dd + tid];

    const float* Ws[3]  = {Wq, Wk, Wv};
    const float* bs[3]  = {bq, bk, bv};
    float*       os[3]  = {gQ, gK, gV};

    for (int w = 0; w < 3; ++w) {
        float acc[12];
        #pragma unroll
        for (int i = 0; i < 12; ++i) acc[i] = 0.f;
        const float* W = Ws[w];
        for (int ks = 0; ks < 8; ++ks) {
            __syncthreads();
            #pragma unroll
            for (int i = 0; i < 32; ++i)
                wch[i][tid] = W[(ks*32 + i)*Dd + tid];
            __syncthreads();
            #pragma unroll
            for (int kk = 0; kk < 32; kk += 4) {
                float w0 = wch[kk+0][tid], w1 = wch[kk+1][tid];
                float w2 = wch[kk+2][tid], w3 = wch[kk+3][tid];
                #pragma unroll
                for (int r = 0; r < 12; ++r) {
                    float4 xv = *(const float4*)&xs[r][ks*32 + kk];
                    acc[r] = fmaf(xv.x, w0, acc[r]);
                    acc[r] = fmaf(xv.y, w1, acc[r]);
                    acc[r] = fmaf(xv.z, w2, acc[r]);
                    acc[r] = fmaf(xv.w, w3, acc[r]);
                }
            }
        }
        float bias = bs[w][tid];
        #pragma unroll
        for (int r = 0; r < 12; ++r)
            os[w][(b*Nn + row0 + r)*Dd + tid] = acc[r] + bias;
        __syncthreads();
    }
}

// ================= smem layout (byte offsets after 1KB align) ======
#define A_HI 0
#define A_LO 49152
#define B_HI 98304
#define B_LO 131072
#define MISC 163840
#define SMEM_BYTES (1024 + 163840 + 8192)

// convert 96x256 fp32 (global) -> A hi/lo bf16 swizzled tiles
__device__ __forceinline__ void convert_A(const float* __restrict__ src, char* smA_hi, char* smA_lo, int tid) {
    for (int idx = tid; idx < 96*32; idx += 256) {
        int row = idx >> 5;
        int c0  = (idx & 31) * 8;
        float4 e0 = *(const float4*)(src + row*Dd + c0);
        float4 e1 = *(const float4*)(src + row*Dd + c0 + 4);
        float h0,l0,h1,l1,h2,l2,h3,l3,h4,l4,h5,l5,h6,l6,h7,l7;
        split_bf(e0.x,h0,l0); split_bf(e0.y,h1,l1); split_bf(e0.z,h2,l2); split_bf(e0.w,h3,l3);
        split_bf(e1.x,h4,l4); split_bf(e1.y,h5,l5); split_bf(e1.z,h6,l6); split_bf(e1.w,h7,l7);
        uint32_t o = a2_off(row, c0);
        *(uint4*)(smA_hi + o) = make_uint4(pack_bf2(h0,h1), pack_bf2(h2,h3), pack_bf2(h4,h5), pack_bf2(h6,h7));
        *(uint4*)(smA_lo + o) = make_uint4(pack_bf2(l0,l1), pack_bf2(l2,l3), pack_bf2(l4,l5), pack_bf2(l6,l7));
    }
}

// stage one 64-k slice of pre-swizzled W (hi+lo, 32KB each)
__device__ __forceinline__ void load_B(int mat, int s, char* smB_hi, char* smB_lo, int tid) {
    const uint4* ghi = (const uint4*)gWB[mat][0][s];
    const uint4* glo = (const uint4*)gWB[mat][1][s];
    uint4* bhi = (uint4*)smB_hi;
    uint4* blo = (uint4*)smB_lo;
    #pragma unroll
    for (int i = 0; i < 8; ++i) {
        bhi[tid + 256*i] = ghi[tid + 256*i];
        blo[tid + 256*i] = glo[tid + 256*i];
    }
}

// one full 96x256x256 GEMM via HMMA, 3-term bf16 split. C[6 mtile][4 ntile][4]
__device__ __forceinline__ void mma_gemm(int mat, char* sm, uint32_t sb, int tid, float C[6][4][4]) {
    int lane = tid & 31;
    int w = tid >> 5;
    int n0 = w * 32;
    int aRow = (lane & 7) + 8 * ((lane >> 3) & 1);
    int aK   = 8 * (lane >> 4);
    int l16  = lane & 15;
    int bN   = l16 & 7;
    int bK   = 8 * (l16 >> 3);

    #pragma unroll
    for (int i = 0; i < 6; ++i)
        #pragma unroll
        for (int j = 0; j < 4; ++j)
            #pragma unroll
            for (int q = 0; q < 4; ++q) C[i][j][q] = 0.f;

    for (int s = 0; s < 4; ++s) {
        load_B(mat, s, sm + B_HI, sm + B_LO, tid);
        __syncthreads();
        #pragma unroll
        for (int t = 0; t < 4; ++t) {
            int k0 = t * 16;
            uint32_t bh[4][2], bl[4][2];
            #pragma unroll
            for (int j = 0; j < 4; ++j) {
                uint32_t bo = b_off(n0 + j*8 + bN, k0 + bK);
                ldsm_x2(bh[j][0], bh[j][1], sb + B_HI + bo);
                ldsm_x2(bl[j][0], bl[j][1], sb + B_LO + bo);
            }
            #pragma unroll
            for (int i = 0; i < 6; ++i) {
                int kg = s*64 + k0 + aK;
                uint32_t ao = a2_off(i*16 + aRow, kg);
                uint32_t ah0,ah1,ah2,ah3, al0,al1,al2,al3;
                ldsm_x4(ah0,ah1,ah2,ah3, sb + A_HI + ao);
                ldsm_x4(al0,al1,al2,al3, sb + A_LO + ao);
                #pragma unroll
                for (int j = 0; j < 4; ++j) {
                    mma16816(C[i][j], ah0,ah1,ah2,ah3, bh[j][0], bh[j][1]);
                    mma16816(C[i][j], al0,al1,al2,al3, bh[j][0], bh[j][1]);
                    mma16816(C[i][j], ah0,ah1,ah2,ah3, bl[j][0], bl[j][1]);
                }
            }
        }
        __syncthreads();
    }
}

// ================= K1: fused dk-GEMM + attention + du-GEMM =================
__global__ __launch_bounds__(256, 1) void fused_kernel(
    const float* __restrict__ edge,
    const float* __restrict__ dist,
    const float* __restrict__ vec,
    const float* __restrict__ bdk, const float* __restrict__ bdu,
    float* __restrict__ out_attn)
{
    extern __shared__ char smraw[];
    uint32_t sb0 = smem_u32(smraw);
    uint32_t alpad = (1024u - (sb0 & 1023u)) & 1023u;
    char* sm = smraw + alpad;
    uint32_t sb = sb0 + alpad;

    char* smA_hi = sm + A_HI;
    char* smA_lo = sm + A_LO;
    float* misc  = (float*)(sm + MISC);
    float* qs    = misc;            // 256
    float* b1s   = qs + 256;        // bdk
    float* b2s   = b1s + 256;       // bdu
    float* scl   = b2s + 256;       // 96
    float* mk    = scl + 96;        // 96
    float* vecs  = mk + 96;         // 288

    int tid = threadIdx.x;
    int lane = tid & 31;
    int w = tid >> 5;
    int g = lane >> 2, tig = lane & 3;
    int n0 = w * 32;
    int b = blockIdx.x / Nn;
    int n = blockIdx.x % Nn;
    int bO = b * Nn;

    if (tid < 256) {
        qs[tid]  = gQ[(bO + n)*Dd + tid];
        b1s[tid] = bdk[tid];
        b2s[tid] = bdu[tid];
    }
    if (tid < 96) {
        unsigned char mm = gMask[(bO + n)*Nn + tid];
        float dd = dist[(bO + n)*Nn + tid];
        float cs = (dd < CUTOFF) ? 0.5f*(cosf(dd*(PI_F/CUTOFF)) + 1.f) : 0.f;
        scl[tid] = mm ? 0.f : cs;
        mk[tid]  = mm ? 0.f : 1.f;
    }
    // vec tile: 288 floats, 256 threads -> two statements (blockDim is 256!)
    {
        size_t vbase = (size_t)(bO + n) * Nn * 3;
        vecs[tid] = vec[vbase + tid];
        if (tid < 32) vecs[256 + tid] = vec[vbase + 256 + tid];
    }

    convert_A(edge + (size_t)(bO + n)*Nn*Dd, smA_hi, smA_lo, tid);
    __syncthreads();

    float C[6][4][4];

    // ---------- GEMM1: dk preact ----------
    mma_gemm(0, sm, sb, tid, C);

    // ---------- epilogue 1: silu + attn weights + probs + As ----------
    #pragma unroll
    for (int i = 0; i < 6; ++i) {
        int m1 = i*16 + g, m2 = m1 + 8;
        float t1 = 0.f, t2 = 0.f;
        #pragma unroll
        for (int j = 0; j < 4; ++j) {
            int c0 = n0 + j*8 + tig*2;
            float bb0 = b1s[c0], bb1 = b1s[c0+1];
            float q0 = qs[c0], q1 = qs[c0+1];
            float d0 = fast_silu(C[i][j][0] + bb0);
            float d1 = fast_silu(C[i][j][1] + bb1);
            float d2 = fast_silu(C[i][j][2] + bb0);
            float d3 = fast_silu(C[i][j][3] + bb1);
            float2 k1v = *(const float2*)&gK[(size_t)(bO + m1)*Dd + c0];
            float2 k2v = *(const float2*)&gK[(size_t)(bO + m2)*Dd + c0];
            t1 = fmaf(d0, q0*k1v.x, fmaf(d1, q1*k1v.y, t1));
            t2 = fmaf(d2, q0*k2v.x, fmaf(d3, q1*k2v.y, t2));
        }
        t1 += __shfl_xor_sync(0xffffffffu, t1, 1);
        t1 += __shfl_xor_sync(0xffffffffu, t1, 2);
        t2 += __shfl_xor_sync(0xffffffffu, t2, 1);
        t2 += __shfl_xor_sync(0xffffffffu, t2, 2);
        float p1 = fast_silu(t1) * scl[m1];
        float p2 = fast_silu(t2) * scl[m2];
        #pragma unroll
        for (int j = 0; j < 4; ++j) {
            int c0 = n0 + j*8 + tig*2;
            float2 v1 = *(const float2*)&gV[(size_t)(bO + m1)*Dd + c0];
            float2 v2 = *(const float2*)&gV[(size_t)(bO + m2)*Dd + c0];
            float a0 = p1*v1.x, a1 = p1*v1.y, a2 = p2*v2.x, a3 = p2*v2.y;
            float h0,l0,h1,l1,h2,l2,h3,l3;
            split_bf(a0,h0,l0); split_bf(a1,h1,l1);
            split_bf(a2,h2,l2); split_bf(a3,h3,l3);
            *(unsigned*)(smA_hi + a2_off(m1, c0)) = pack_bf2(h0,h1);
            *(unsigned*)(smA_lo + a2_off(m1, c0)) = pack_bf2(l0,l1);
            *(unsigned*)(smA_hi + a2_off(m2, c0)) = pack_bf2(h2,h3);
            *(unsigned*)(smA_lo + a2_off(m2, c0)) = pack_bf2(l2,l3);
        }
    }
    __syncthreads();

    // ---------- attn = column sums of As ----------
    if (tid < 256) {
        float s = 0.f;
        #pragma unroll 4
        for (int m = 0; m < 96; ++m) {
            uint32_t o = a2_off(m, tid);
            float hv = __bfloat162float(*(const __nv_bfloat16*)(smA_hi + o));
            float lv = __bfloat162float(*(const __nv_bfloat16*)(smA_lo + o));
            s += hv + lv;
        }
        out_attn[(bO + n)*Dd + tid] = s;
    }
    __syncthreads();

    // ---------- GEMM2: du_in = As @ Wdu ----------
    mma_gemm(1, sm, sb, tid, C);

    // ---------- epilogue 2: din = (C + bdu)*keep -> fp32 plane (reuse A region) ----------
    float* din = (float*)(sm + A_HI);   // [96][256] fp32 = 96KB
    #pragma unroll
    for (int i = 0; i < 6; ++i) {
        int m1 = i*16 + g, m2 = m1 + 8;
        float k1 = mk[m1], k2 = mk[m2];
        #pragma unroll
        for (int j = 0; j < 4; ++j) {
            int c0 = n0 + j*8 + tig*2;
            float2 d1 = make_float2((C[i][j][0] + b2s[c0]) * k1, (C[i][j][1] + b2s[c0+1]) * k1);
            float2 d2 = make_float2((C[i][j][2] + b2s[c0]) * k2, (C[i][j][3] + b2s[c0+1]) * k2);
            *(float2*)&din[m1*Dd + c0] = d1;
            *(float2*)&din[m2*Dd + c0] = d2;
        }
    }
    __syncthreads();

    // ---------- du[comp][c] = sum_m din[m][c] * vec[m][comp] ----------
    if (tid < 256) {
        float a0 = 0.f, a1 = 0.f, a2 = 0.f;
        #pragma unroll 4
        for (int m = 0; m < 96; ++m) {
            float v = din[m*Dd + tid];
            a0 = fmaf(v, vecs[m*3+0], a0);
            a1 = fmaf(v, vecs[m*3+1], a1);
            a2 = fmaf(v, vecs[m*3+2], a2);
        }
        gDU[((bO + n)*3 + 0)*Dd + tid] = a0;
        gDU[((bO + n)*3 + 1)*Dd + tid] = a1;
        gDU[((bO + n)*3 + 2)*Dd + tid] = a2;
    }
}

// ================= K2: w = du @ Wdih (SIMT, small) =================
__global__ __launch_bounds__(256) void w_kernel(const float* __restrict__ Wdih)
{
    __shared__ float dus[12*256];
    __shared__ float wch[16][512];
    int tid = threadIdx.x;
    int b  = blockIdx.x / 24;
    int ng = blockIdx.x % 24;
    int nbase = ng * 4;

    size_t dbase = (size_t)(b*Nn + nbase) * 3 * Dd;
    #pragma unroll
    for (int i = 0; i < 12; ++i)
        dus[tid + 256*i] = gDU[dbase + tid + 256*i];

    float acc0[12], acc1[12];
    #pragma unroll
    for (int q = 0; q < 12; ++q) { acc0[q] = 0.f; acc1[q] = 0.f; }

    for (int ks = 0; ks < 16; ++ks) {
        __syncthreads();
        #pragma unroll
        for (int i = 0; i < 32; ++i) {
            int lin = tid + 256*i;
            int row = lin >> 9;
            int col = lin & 511;
            wch[row][col] = Wdih[(ks*16 + row)*512 + col];
        }
        __syncthreads();
        #pragma unroll
        for (int kk = 0; kk < 16; ++kk) {
            float w0 = wch[kk][tid];
            float w1 = wch[kk][tid + 256];
            #pragma unroll
            for (int q = 0; q < 12; ++q) {
                float xv = dus[q*256 + ks*16 + kk];
                acc0[q] = fmaf(xv, w0, acc0[q]);
                acc1[q] = fmaf(xv, w1, acc1[q]);
            }
        }
    }
    #pragma unroll
    for (int q = 0; q < 12; ++q) {
        int ni = q / 3, c = q % 3;
        gWS[((b*Nn + nbase + ni)*3 + c)*Dd + tid] = acc0[q];
        gWT[((b*Nn + nbase + ni)*3 + c)*Dd + tid] = acc1[q];
    }
}

// ================= K3: ipe = silu(E @ Wea + bea) * (ws . wt) =================
__global__ __launch_bounds__(256, 1) void ipe_kernel(
    const float* __restrict__ edge,
    const float* __restrict__ bea,
    float* __restrict__ out_ipe)
{
    extern __shared__ char smraw[];
    uint32_t sb0 = smem_u32(smraw);
    uint32_t alpad = (1024u - (sb0 & 1023u)) & 1023u;
    char* sm = smraw + alpad;
    uint32_t sb = sb0 + alpad;

    char* smA_hi = sm + A_HI;
    char* smA_lo = sm + A_LO;
    float* misc  = (float*)(sm + MISC);
    float* bs    = misc;            // 256
    float* wsr   = bs + 256;        // 3x256

    int tid = threadIdx.x;
    int lane = tid & 31;
    int w = tid >> 5;
    int g = lane >> 2, tig = lane & 3;
    int n0 = w * 32;
    int b = blockIdx.x / Nn;
    int n = blockIdx.x % Nn;
    int bO = b * Nn;

    if (tid < 256) {
        bs[tid] = bea[tid];
        size_t wbase = (size_t)(bO + n) * 3 * Dd;
        #pragma unroll
        for (int i = 0; i < 3; ++i) wsr[i*256 + tid] = gWS[wbase + i*256 + tid];
    }
    convert_A(edge + (size_t)(bO + n)*Nn*Dd, smA_hi, smA_lo, tid);
    __syncthreads();

    float C[6][4][4];
    mma_gemm(2, sm, sb, tid, C);

    #pragma unroll
    for (int i = 0; i < 6; ++i) {
        int m1 = i*16 + g, m2 = m1 + 8;
        const float* wt1 = &gWT[(size_t)((bO + m1)*3)*Dd];
        const float* wt2 = &gWT[(size_t)((bO + m2)*3)*Dd];
        float* o1 = &out_ipe[((size_t)(bO + n)*Nn + m1)*Dd];
        float* o2 = &out_ipe[((size_t)(bO + n)*Nn + m2)*Dd];
        #pragma unroll
        for (int j = 0; j < 4; ++j) {
            int c0 = n0 + j*8 + tig*2;
            float2 w0 = *(const float2*)&wsr[0*256 + c0];
            float2 w1 = *(const float2*)&wsr[1*256 + c0];
            float2 w2 = *(const float2*)&wsr[2*256 + c0];
            float2 bb = *(const float2*)&bs[c0];
            float2 t10 = *(const float2*)(wt1 + c0);
            float2 t11 = *(const float2*)(wt1 + 256 + c0);
            float2 t12 = *(const float2*)(wt1 + 512 + c0);
            float2 t20 = *(const float2*)(wt2 + c0);
            float2 t21 = *(const float2*)(wt2 + 256 + c0);
            float2 t22 = *(const float2*)(wt2 + 512 + c0);
            float2 r1, r2;
            r1.x = fast_silu(C[i][j][0] + bb.x) * (w0.x*t10.x + w1.x*t11.x + w2.x*t12.x);
            r1.y = fast_silu(C[i][j][1] + bb.y) * (w0.y*t10.y + w1.y*t11.y + w2.y*t12.y);
            r2.x = fast_silu(C[i][j][2] + bb.x) * (w0.x*t20.x + w1.x*t21.x + w2.x*t22.x);
            r2.y = fast_silu(C[i][j][3] + bb.y) * (w0.y*t20.y + w1.y*t21.y + w2.y*t22.y);
            *(float2*)(o1 + c0) = r1;
            *(float2*)(o2 + c0) = r2;
        }
    }
}

// ================= launch =================
extern "C" void kernel_launch(void* const* d_in, const int* in_sizes, int n_in,
                              void* d_out, int out_size)
{
    const float* x    = (const float*)d_in[0];
    const float* vec  = (const float*)d_in[1];
    const float* dist = (const float*)d_in[2];
    const float* edge = (const float*)d_in[3];
    const unsigned char* mraw = (const unsigned char*)d_in[4];
    const float* Wq   = (const float*)d_in[5];
    const float* bq   = (const float*)d_in[6];
    const float* Wk   = (const float*)d_in[7];
    const float* bk   = (const float*)d_in[8];
    const float* Wv   = (const float*)d_in[9];
    const float* bv   = (const float*)d_in[10];
    const float* Wdk  = (const float*)d_in[11];
    const float* bdk  = (const float*)d_in[12];
    const float* Wdu  = (const float*)d_in[13];
    const float* bdu  = (const float*)d_in[14];
    const float* Wdih = (const float*)d_in[15];
    const float* Wea  = (const float*)d_in[16];
    const float* bea  = (const float*)d_in[17];

    float* out_attn = (float*)d_out;                    // (B,N,D)
    float* out_ipe  = out_attn + Bb*Nn*Dd;              // (B,N,N,D)

    cudaFuncSetAttribute(fused_kernel, cudaFuncAttributeMaxDynamicSharedMemorySize, SMEM_BYTES);
    cudaFuncSetAttribute(ipe_kernel,   cudaFuncAttributeMaxDynamicSharedMemorySize, SMEM_BYTES);

    mask_conv_kernel<<<1, 256>>>(mraw);
    wconv_kernel<<<384, 256>>>(Wdk, Wdu, Wea);
    qkv_kernel<<<64, 256>>>(x, Wq, bq, Wk, bk, Wv, bv);
    fused_kernel<<<Bb*Nn, 256, SMEM_BYTES>>>(edge, dist, vec, bdk, bdu, out_attn);
    w_kernel<<<Bb*24, 256>>>(Wdih);
    ipe_kernel<<<Bb*Nn, 256, SMEM_BYTES>>>(edge, bea, out_ipe);
}

// round 8
// speedup vs baseline: 2.2657x; 1.0787x over previous
#include <cuda_runtime.h>
#include <cuda_bf16.h>
#include <cstdint>

#define Bb 8
#define Nn 96
#define Dd 256
#define CUTOFF 5.0f
#define PI_F 3.14159265358979f

// ================= scratch (device globals; no allocation allowed) =============
__device__ float gQ[Bb*Nn*Dd];
__device__ float gK[Bb*Nn*Dd];
__device__ float gV[Bb*Nn*Dd];
__device__ float gDU[Bb*Nn*3*Dd];
__device__ float gWS[Bb*Nn*3*Dd];
__device__ float gWT[Bb*Nn*3*Dd];
__device__ unsigned char gMask[Bb*Nn*Nn];
// Pre-converted weights: [mat: dk,du,ea][prec: hi,lo][k-slice 0..3][32KB swizzled B tile]
// B tile per slice: [256 n][64 k] bf16, 8x64 atoms, XOR-swizzled (ldmatrix .col operand).
__device__ __align__(16) unsigned char gWB[3][2][4][32768];

// ================= helpers =================
__device__ __forceinline__ uint32_t smem_u32(const void* p) {
    uint32_t a;
    asm("{ .reg .u64 t; cvta.to.shared.u64 t, %1; cvt.u32.u64 %0, t; }" : "=r"(a) : "l"(p));
    return a;
}
__device__ __forceinline__ uint32_t swz(uint32_t b) { return b ^ ((b >> 3) & 0x70); }

// B slice byte offset: [256 n][64 k] bf16, atom = 8 n-rows x 128B
__device__ __forceinline__ uint32_t b_off(int n, int k) {
    uint32_t byte = ((n >> 3) << 10) + ((n & 7) << 7) + (k << 1);
    return swz(byte);
}
// A tile byte offset: [96 rows][256 cols] bf16, atoms 8r x 64c, 12 atom-rows per atom-col
__device__ __forceinline__ uint32_t a2_off(int row, int col) {
    uint32_t byte = (uint32_t)(((col >> 6) * 12 + (row >> 3)) << 10) + ((row & 7) << 7) + ((col & 63) << 1);
    return swz(byte);
}

__device__ __forceinline__ unsigned pack_bf2(float a, float b) {
    __nv_bfloat162 h = __floats2bfloat162_rn(a, b);
    return *reinterpret_cast<unsigned*>(&h);
}
__device__ __forceinline__ void split_bf(float x, float& hi, float& lo) {
    __nv_bfloat16 h = __float2bfloat16_rn(x);
    hi = __bfloat162float(h);
    lo = x - hi;
}

__device__ __forceinline__ void ldsm_x4(uint32_t& r0, uint32_t& r1, uint32_t& r2, uint32_t& r3, uint32_t addr) {
    asm volatile("ldmatrix.sync.aligned.m8n8.x4.shared.b16 {%0,%1,%2,%3}, [%4];"
                 : "=r"(r0), "=r"(r1), "=r"(r2), "=r"(r3) : "r"(addr));
}
__device__ __forceinline__ void mma16816(float* c, uint32_t a0, uint32_t a1, uint32_t a2, uint32_t a3,
                                         uint32_t b0, uint32_t b1) {
    asm volatile("mma.sync.aligned.m16n8k16.row.col.f32.bf16.bf16.f32 "
                 "{%0,%1,%2,%3}, {%4,%5,%6,%7}, {%8,%9}, {%0,%1,%2,%3};"
                 : "+f"(c[0]), "+f"(c[1]), "+f"(c[2]), "+f"(c[3])
                 : "r"(a0), "r"(a1), "r"(a2), "r"(a3), "r"(b0), "r"(b1));
}
__device__ __forceinline__ void cp16(uint32_t smem_addr, const void* gptr) {
    asm volatile("cp.async.cg.shared.global [%0], [%1], 16;" :: "r"(smem_addr), "l"(gptr));
}
#define CP_COMMIT() asm volatile("cp.async.commit_group;" ::: "memory")
#define CP_WAIT0()  asm volatile("cp.async.wait_group 0;" ::: "memory")

// ================= FMA-only silu =================
__device__ __forceinline__ float fast_silu(float x) {
    float t = x * -1.4426950408889634f;
    t = fminf(fmaxf(t, -30.0f), 30.0f);
    float fn = rintf(t);
    float f  = t - fn;
    float p = 1.3333558e-3f;
    p = fmaf(p, f, 9.6181291e-3f);
    p = fmaf(p, f, 5.5504109e-2f);
    p = fmaf(p, f, 2.4022651e-1f);
    p = fmaf(p, f, 6.9314718e-1f);
    p = fmaf(p, f, 1.0f);
    float sc = __int_as_float(((int)fn + 127) << 23);
    float e = p * sc;
    float d = 1.0f + e;
    float y = __int_as_float(0x7EF311C3u - __float_as_int(d));
    y = y * (2.0f - d * y);
    y = y * (2.0f - d * y);
    y = y * (2.0f - d * y);
    return x * y;
}

// ================= mask dtype canonicalization =================
__global__ void mask_conv_kernel(const unsigned char* __restrict__ raw) {
    __shared__ int mode_s;
    int tid = threadIdx.x;
    if (tid == 0) mode_s = 0;
    __syncthreads();
    int local = 0;
    const int NEL = Bb*Nn*Nn;
    for (int i = tid; i < NEL; i += 256) {
        unsigned char bch = raw[i];
        if (bch != 0 && (i & 3) != 0) {
            if (bch == 0x80 || bch == 0x3F) local |= 2;
            else                            local |= 1;
        }
    }
    if (local) atomicOr(&mode_s, local);
    __syncthreads();
    int mode = mode_s;
    for (int i = tid; i < NEL; i += 256) {
        unsigned char v;
        if (mode & 1)      v = (raw[i] != 0);
        else if (mode & 2) v = (((const float*)raw)[i] != 0.0f);
        else               v = (((const int*)raw)[i]   != 0);
        gMask[i] = v;
    }
}

// ================= W pre-convert: W[k][n] fp32 -> bf16 hi/lo slices [n][k], pre-swizzled ====
__global__ __launch_bounds__(256) void wconv_kernel(
    const float* __restrict__ Wdk, const float* __restrict__ Wdu, const float* __restrict__ Wea)
{
    int idx = blockIdx.x * 256 + threadIdx.x;      // 3*256*128
    int mat = idx / (256*128);
    int rem = idx % (256*128);
    int n   = rem / 128;
    int kp  = rem % 128;
    int k0  = kp * 2;
    const float* W = (mat == 0) ? Wdk : (mat == 1) ? Wdu : Wea;
    float w0 = W[k0*Dd + n];
    float w1 = W[(k0+1)*Dd + n];
    float h0, l0, h1, l1;
    split_bf(w0, h0, l0);
    split_bf(w1, h1, l1);
    int slice = k0 >> 6;
    int kk = k0 & 63;
    uint32_t off = b_off(n, kk);
    *(unsigned*)(&gWB[mat][0][slice][off]) = pack_bf2(h0, h1);
    *(unsigned*)(&gWB[mat][1][slice][off]) = pack_bf2(l0, l1);
}

// ================= K0: Q/K/V = x @ W + b (SIMT, small) =================
__global__ __launch_bounds__(256) void qkv_kernel(
    const float* __restrict__ x,
    const float* __restrict__ Wq, const float* __restrict__ bq,
    const float* __restrict__ Wk, const float* __restrict__ bk,
    const float* __restrict__ Wv, const float* __restrict__ bv)
{
    __shared__ float xs[12][256];
    __shared__ float wch[32][256];
    int tid = threadIdx.x;
    int b   = blockIdx.x >> 3;
    int rg  = blockIdx.x & 7;
    int row0 = rg * 12;

    #pragma unroll
    for (int i = 0; i < 12; ++i)
        xs[i][tid] = x[(b*Nn + row0 + i)*Dd + tid];

    const float* Ws[3]  = {Wq, Wk, Wv};
    const float* bs[3]  = {bq, bk, bv};
    float*       os[3]  = {gQ, gK, gV};

    for (int w = 0; w < 3; ++w) {
        float acc[12];
        #pragma unroll
        for (int i = 0; i < 12; ++i) acc[i] = 0.f;
        const float* W = Ws[w];
        for (int ks = 0; ks < 8; ++ks) {
            __syncthreads();
            #pragma unroll
            for (int i = 0; i < 32; ++i)
                wch[i][tid] = W[(ks*32 + i)*Dd + tid];
            __syncthreads();
            #pragma unroll
            for (int kk = 0; kk < 32; kk += 4) {
                float w0 = wch[kk+0][tid], w1 = wch[kk+1][tid];
                float w2 = wch[kk+2][tid], w3 = wch[kk+3][tid];
                #pragma unroll
                for (int r = 0; r < 12; ++r) {
                    float4 xv = *(const float4*)&xs[r][ks*32 + kk];
                    acc[r] = fmaf(xv.x, w0, acc[r]);
                    acc[r] = fmaf(xv.y, w1, acc[r]);
                    acc[r] = fmaf(xv.z, w2, acc[r]);
                    acc[r] = fmaf(xv.w, w3, acc[r]);
                }
            }
        }
        float bias = bs[w][tid];
        #pragma unroll
        for (int r = 0; r < 12; ++r)
            os[w][(b*Nn + row0 + r)*Dd + tid] = acc[r] + bias;
        __syncthreads();
    }
}

// ================= smem layout (byte offsets after 1KB align) ======
#define A_HI 0
#define A_LO 49152
#define B0   98304
#define B1   131072
#define MISC 163840
#define SMEM_BYTES (1024 + 163840 + 8192)
#define NTHREADS 512

// convert 96x256 fp32 (global) -> A hi/lo bf16 swizzled tiles
__device__ __forceinline__ void convert_A(const float* __restrict__ src, char* smA_hi, char* smA_lo, int tid) {
    for (int idx = tid; idx < 96*32; idx += NTHREADS) {
        int row = idx >> 5;
        int c0  = (idx & 31) * 8;
        float4 e0 = *(const float4*)(src + row*Dd + c0);
        float4 e1 = *(const float4*)(src + row*Dd + c0 + 4);
        float h0,l0,h1,l1,h2,l2,h3,l3,h4,l4,h5,l5,h6,l6,h7,l7;
        split_bf(e0.x,h0,l0); split_bf(e0.y,h1,l1); split_bf(e0.z,h2,l2); split_bf(e0.w,h3,l3);
        split_bf(e1.x,h4,l4); split_bf(e1.y,h5,l5); split_bf(e1.z,h6,l6); split_bf(e1.w,h7,l7);
        uint32_t o = a2_off(row, c0);
        *(uint4*)(smA_hi + o) = make_uint4(pack_bf2(h0,h1), pack_bf2(h2,h3), pack_bf2(h4,h5), pack_bf2(h6,h7));
        *(uint4*)(smA_lo + o) = make_uint4(pack_bf2(l0,l1), pack_bf2(l2,l3), pack_bf2(l4,l5), pack_bf2(l6,l7));
    }
}

// async-stage one 32KB pre-swizzled B slice
__device__ __forceinline__ void cp_slice(uint32_t smem_dst, const unsigned char* gsrc, int tid) {
    #pragma unroll
    for (int i = 0; i < 4; ++i) {
        int e = tid + NTHREADS*i;      // 2048 x 16B = 32KB
        cp16(smem_dst + e*16, gsrc + e*16);
    }
}

// one full 96x256x256 GEMM via HMMA, 3-term bf16 split, cp.async-pipelined B.
// 16 warps: wg = w>>3 (m rows wg*48..+47, i<3), wn = w&7 (n cols wn*32..+31, j<4).
// C[3][4][4].
__device__ __forceinline__ void mma_gemm(int mat, uint32_t sb, int tid, float C[3][4][4]) {
    int lane = tid & 31;
    int w = tid >> 5;
    int wg = w >> 3;
    int n0 = (w & 7) * 32;
    int rowb = wg * 48;
    int aRow = (lane & 7) + 8 * ((lane >> 3) & 1);
    int aK   = 8 * (lane >> 4);
    // B ldmatrix.x4 addressing: matrix q = lane>>3 -> n-subtile (q>>1)*8, k-half (q&1)*8
    int bMat = lane >> 3;
    int bRow = lane & 7;
    int bNo  = (bMat >> 1) * 8;
    int bKo  = (bMat & 1) * 8;

    #pragma unroll
    for (int i = 0; i < 3; ++i)
        #pragma unroll
        for (int j = 0; j < 4; ++j)
            #pragma unroll
            for (int q = 0; q < 4; ++q) C[i][j][q] = 0.f;

    // prologue: Bh(0) -> B0
    cp_slice(sb + B0, gWB[mat][0][0], tid);
    CP_COMMIT(); CP_WAIT0();
    __syncthreads();

    for (int s = 0; s < 4; ++s) {
        // start Bl(s) -> B1 (overlaps with hi-term compute)
        cp_slice(sb + B1, gWB[mat][1][s], tid);
        CP_COMMIT();

        // phase A: Ah*Bh + Al*Bh from B0
        #pragma unroll
        for (int t = 0; t < 4; ++t) {
            int k0 = t * 16;
            uint32_t bh[4][2];
            #pragma unroll
            for (int jp = 0; jp < 2; ++jp) {
                uint32_t bo = b_off(n0 + jp*16 + bNo + bRow, k0 + bKo);
                ldsm_x4(bh[jp*2][0], bh[jp*2][1], bh[jp*2+1][0], bh[jp*2+1][1], sb + B0 + bo);
            }
            #pragma unroll
            for (int i = 0; i < 3; ++i) {
                uint32_t ao = a2_off(rowb + i*16 + aRow, s*64 + k0 + aK);
                uint32_t ah0,ah1,ah2,ah3, al0,al1,al2,al3;
                ldsm_x4(ah0,ah1,ah2,ah3, sb + A_HI + ao);
                ldsm_x4(al0,al1,al2,al3, sb + A_LO + ao);
                #pragma unroll
                for (int j = 0; j < 4; ++j) {
                    mma16816(C[i][j], ah0,ah1,ah2,ah3, bh[j][0], bh[j][1]);
                    mma16816(C[i][j], al0,al1,al2,al3, bh[j][0], bh[j][1]);
                }
            }
        }
        CP_WAIT0();
        __syncthreads();

        // start Bh(s+1) -> B0 (overlaps with lo-term compute)
        if (s < 3) { cp_slice(sb + B0, gWB[mat][0][s+1], tid); CP_COMMIT(); }

        // phase B: Ah*Bl from B1
        #pragma unroll
        for (int t = 0; t < 4; ++t) {
            int k0 = t * 16;
            uint32_t bl[4][2];
            #pragma unroll
            for (int jp = 0; jp < 2; ++jp) {
                uint32_t bo = b_off(n0 + jp*16 + bNo + bRow, k0 + bKo);
                ldsm_x4(bl[jp*2][0], bl[jp*2][1], bl[jp*2+1][0], bl[jp*2+1][1], sb + B1 + bo);
            }
            #pragma unroll
            for (int i = 0; i < 3; ++i) {
                uint32_t ao = a2_off(rowb + i*16 + aRow, s*64 + k0 + aK);
                uint32_t ah0,ah1,ah2,ah3;
                ldsm_x4(ah0,ah1,ah2,ah3, sb + A_HI + ao);
                #pragma unroll
                for (int j = 0; j < 4; ++j)
                    mma16816(C[i][j], ah0,ah1,ah2,ah3, bl[j][0], bl[j][1]);
            }
        }
        CP_WAIT0();
        __syncthreads();
    }
}

// ================= K1: fused dk-GEMM + attention + du-GEMM =================
__global__ __launch_bounds__(NTHREADS, 1) void fused_kernel(
    const float* __restrict__ edge,
    const float* __restrict__ dist,
    const float* __restrict__ vec,
    const float* __restrict__ bdk, const float* __restrict__ bdu,
    float* __restrict__ out_attn)
{
    extern __shared__ char smraw[];
    uint32_t sb0 = smem_u32(smraw);
    uint32_t alpad = (1024u - (sb0 & 1023u)) & 1023u;
    char* sm = smraw + alpad;
    uint32_t sb = sb0 + alpad;

    char* smA_hi = sm + A_HI;
    char* smA_lo = sm + A_LO;
    float* misc  = (float*)(sm + MISC);
    float* qs    = misc;            // 256
    float* b1s   = qs + 256;        // bdk
    float* b2s   = b1s + 256;       // bdu
    float* scl   = b2s + 256;       // 96
    float* mk    = scl + 96;        // 96
    float* vecs  = mk + 96;         // 288

    int tid = threadIdx.x;
    int lane = tid & 31;
    int w = tid >> 5;
    int wg = w >> 3;
    int g = lane >> 2, tig = lane & 3;
    int n0 = (w & 7) * 32;
    int rowb = wg * 48;
    int b = blockIdx.x / Nn;
    int n = blockIdx.x % Nn;
    int bO = b * Nn;

    if (tid < 256) {
        qs[tid]  = gQ[(bO + n)*Dd + tid];
        b1s[tid] = bdk[tid];
        b2s[tid] = bdu[tid];
    }
    if (tid < 96) {
        unsigned char mm = gMask[(bO + n)*Nn + tid];
        float dd = dist[(bO + n)*Nn + tid];
        float cs = (dd < CUTOFF) ? 0.5f*(cosf(dd*(PI_F/CUTOFF)) + 1.f) : 0.f;
        scl[tid] = mm ? 0.f : cs;
        mk[tid]  = mm ? 0.f : 1.f;
    }
    if (tid < 288) vecs[tid] = vec[(size_t)(bO + n)*Nn*3 + tid];

    convert_A(edge + (size_t)(bO + n)*Nn*Dd, smA_hi, smA_lo, tid);
    __syncthreads();

    float C[3][4][4];

    // ---------- GEMM1: dk preact ----------
    mma_gemm(0, sb, tid, C);

    // ---------- epilogue 1: silu + attn weights + probs + As ----------
    #pragma unroll
    for (int i = 0; i < 3; ++i) {
        int m1 = rowb + i*16 + g, m2 = m1 + 8;
        float t1 = 0.f, t2 = 0.f;
        #pragma unroll
        for (int j = 0; j < 4; ++j) {
            int c0 = n0 + j*8 + tig*2;
            float bb0 = b1s[c0], bb1 = b1s[c0+1];
            float q0 = qs[c0], q1 = qs[c0+1];
            float d0 = fast_silu(C[i][j][0] + bb0);
            float d1 = fast_silu(C[i][j][1] + bb1);
            float d2 = fast_silu(C[i][j][2] + bb0);
            float d3 = fast_silu(C[i][j][3] + bb1);
            float2 k1v = *(const float2*)&gK[(size_t)(bO + m1)*Dd + c0];
            float2 k2v = *(const float2*)&gK[(size_t)(bO + m2)*Dd + c0];
            t1 = fmaf(d0, q0*k1v.x, fmaf(d1, q1*k1v.y, t1));
            t2 = fmaf(d2, q0*k2v.x, fmaf(d3, q1*k2v.y, t2));
        }
        t1 += __shfl_xor_sync(0xffffffffu, t1, 1);
        t1 += __shfl_xor_sync(0xffffffffu, t1, 2);
        t2 += __shfl_xor_sync(0xffffffffu, t2, 1);
        t2 += __shfl_xor_sync(0xffffffffu, t2, 2);
        float p1 = fast_silu(t1) * scl[m1];
        float p2 = fast_silu(t2) * scl[m2];
        #pragma unroll
        for (int j = 0; j < 4; ++j) {
            int c0 = n0 + j*8 + tig*2;
            float2 v1 = *(const float2*)&gV[(size_t)(bO + m1)*Dd + c0];
            float2 v2 = *(const float2*)&gV[(size_t)(bO + m2)*Dd + c0];
            float a0 = p1*v1.x, a1 = p1*v1.y, a2 = p2*v2.x, a3 = p2*v2.y;
            float h0,l0,h1,l1,h2,l2,h3,l3;
            split_bf(a0,h0,l0); split_bf(a1,h1,l1);
            split_bf(a2,h2,l2); split_bf(a3,h3,l3);
            *(unsigned*)(smA_hi + a2_off(m1, c0)) = pack_bf2(h0,h1);
            *(unsigned*)(smA_lo + a2_off(m1, c0)) = pack_bf2(l0,l1);
            *(unsigned*)(smA_hi + a2_off(m2, c0)) = pack_bf2(h2,h3);
            *(unsigned*)(smA_lo + a2_off(m2, c0)) = pack_bf2(l2,l3);
        }
    }
    __syncthreads();

    // ---------- attn = column sums of As ----------
    if (tid < 256) {
        float s = 0.f;
        #pragma unroll 4
        for (int m = 0; m < 96; ++m) {
            uint32_t o = a2_off(m, tid);
            float hv = __bfloat162float(*(const __nv_bfloat16*)(smA_hi + o));
            float lv = __bfloat162float(*(const __nv_bfloat16*)(smA_lo + o));
            s += hv + lv;
        }
        out_attn[(bO + n)*Dd + tid] = s;
    }
    __syncthreads();

    // ---------- GEMM2: du_in = As @ Wdu ----------
    mma_gemm(1, sb, tid, C);

    // ---------- epilogue 2: din = (C + bdu)*keep -> fp32 plane (reuse A region) ----------
    float* din = (float*)(sm + A_HI);   // [96][256] fp32 = 96KB
    #pragma unroll
    for (int i = 0; i < 3; ++i) {
        int m1 = rowb + i*16 + g, m2 = m1 + 8;
        float k1 = mk[m1], k2 = mk[m2];
        #pragma unroll
        for (int j = 0; j < 4; ++j) {
            int c0 = n0 + j*8 + tig*2;
            float2 d1 = make_float2((C[i][j][0] + b2s[c0]) * k1, (C[i][j][1] + b2s[c0+1]) * k1);
            float2 d2 = make_float2((C[i][j][2] + b2s[c0]) * k2, (C[i][j][3] + b2s[c0+1]) * k2);
            *(float2*)&din[m1*Dd + c0] = d1;
            *(float2*)&din[m2*Dd + c0] = d2;
        }
    }
    __syncthreads();

    // ---------- du[comp][c] = sum_m din[m][c] * vec[m][comp] ----------
    if (tid < 256) {
        float a0 = 0.f, a1 = 0.f, a2 = 0.f;
        #pragma unroll 4
        for (int m = 0; m < 96; ++m) {
            float v = din[m*Dd + tid];
            a0 = fmaf(v, vecs[m*3+0], a0);
            a1 = fmaf(v, vecs[m*3+1], a1);
            a2 = fmaf(v, vecs[m*3+2], a2);
        }
        gDU[((bO + n)*3 + 0)*Dd + tid] = a0;
        gDU[((bO + n)*3 + 1)*Dd + tid] = a1;
        gDU[((bO + n)*3 + 2)*Dd + tid] = a2;
    }
}

// ================= K2: w = du @ Wdih (SIMT, small) =================
__global__ __launch_bounds__(256) void w_kernel(const float* __restrict__ Wdih)
{
    __shared__ float dus[12*256];
    __shared__ float wch[16][512];
    int tid = threadIdx.x;
    int b  = blockIdx.x / 24;
    int ng = blockIdx.x % 24;
    int nbase = ng * 4;

    size_t dbase = (size_t)(b*Nn + nbase) * 3 * Dd;
    #pragma unroll
    for (int i = 0; i < 12; ++i)
        dus[tid + 256*i] = gDU[dbase + tid + 256*i];

    float acc0[12], acc1[12];
    #pragma unroll
    for (int q = 0; q < 12; ++q) { acc0[q] = 0.f; acc1[q] = 0.f; }

    for (int ks = 0; ks < 16; ++ks) {
        __syncthreads();
        #pragma unroll
        for (int i = 0; i < 32; ++i) {
            int lin = tid + 256*i;
            int row = lin >> 9;
            int col = lin & 511;
            wch[row][col] = Wdih[(ks*16 + row)*512 + col];
        }
        __syncthreads();
        #pragma unroll
        for (int kk = 0; kk < 16; ++kk) {
            float w0 = wch[kk][tid];
            float w1 = wch[kk][tid + 256];
            #pragma unroll
            for (int q = 0; q < 12; ++q) {
                float xv = dus[q*256 + ks*16 + kk];
                acc0[q] = fmaf(xv, w0, acc0[q]);
                acc1[q] = fmaf(xv, w1, acc1[q]);
            }
        }
    }
    #pragma unroll
    for (int q = 0; q < 12; ++q) {
        int ni = q / 3, c = q % 3;
        gWS[((b*Nn + nbase + ni)*3 + c)*Dd + tid] = acc0[q];
        gWT[((b*Nn + nbase + ni)*3 + c)*Dd + tid] = acc1[q];
    }
}

// ================= K3: ipe = silu(E @ Wea + bea) * (ws . wt) =================
__global__ __launch_bounds__(NTHREADS, 1) void ipe_kernel(
    const float* __restrict__ edge,
    const float* __restrict__ bea,
    float* __restrict__ out_ipe)
{
    extern __shared__ char smraw[];
    uint32_t sb0 = smem_u32(smraw);
    uint32_t alpad = (1024u - (sb0 & 1023u)) & 1023u;
    char* sm = smraw + alpad;
    uint32_t sb = sb0 + alpad;

    char* smA_hi = sm + A_HI;
    char* smA_lo = sm + A_LO;
    float* misc  = (float*)(sm + MISC);
    float* bs    = misc;            // 256
    float* wsr   = bs + 256;        // 3x256

    int tid = threadIdx.x;
    int lane = tid & 31;
    int w = tid >> 5;
    int wg = w >> 3;
    int g = lane >> 2, tig = lane & 3;
    int n0 = (w & 7) * 32;
    int rowb = wg * 48;
    int b = blockIdx.x / Nn;
    int n = blockIdx.x % Nn;
    int bO = b * Nn;

    if (tid < 256) {
        bs[tid] = bea[tid];
        size_t wbase = (size_t)(bO + n) * 3 * Dd;
        #pragma unroll
        for (int i = 0; i < 3; ++i) wsr[i*256 + tid] = gWS[wbase + i*256 + tid];
    }
    convert_A(edge + (size_t)(bO + n)*Nn*Dd, smA_hi, smA_lo, tid);
    __syncthreads();

    float C[3][4][4];
    mma_gemm(2, sb, tid, C);

    #pragma unroll
    for (int i = 0; i < 3; ++i) {
        int m1 = rowb + i*16 + g, m2 = m1 + 8;
        const float* wt1 = &gWT[(size_t)((bO + m1)*3)*Dd];
        const float* wt2 = &gWT[(size_t)((bO + m2)*3)*Dd];
        float* o1 = &out_ipe[((size_t)(bO + n)*Nn + m1)*Dd];
        float* o2 = &out_ipe[((size_t)(bO + n)*Nn + m2)*Dd];
        #pragma unroll
        for (int j = 0; j < 4; ++j) {
            int c0 = n0 + j*8 + tig*2;
            float2 w0 = *(const float2*)&wsr[0*256 + c0];
            float2 w1 = *(const float2*)&wsr[1*256 + c0];
            float2 w2 = *(const float2*)&wsr[2*256 + c0];
            float2 bb = *(const float2*)&bs[c0];
            float2 t10 = *(const float2*)(wt1 + c0);
            float2 t11 = *(const float2*)(wt1 + 256 + c0);
            float2 t12 = *(const float2*)(wt1 + 512 + c0);
            float2 t20 = *(const float2*)(wt2 + c0);
            float2 t21 = *(const float2*)(wt2 + 256 + c0);
            float2 t22 = *(const float2*)(wt2 + 512 + c0);
            float2 r1, r2;
            r1.x = fast_silu(C[i][j][0] + bb.x) * (w0.x*t10.x + w1.x*t11.x + w2.x*t12.x);
            r1.y = fast_silu(C[i][j][1] + bb.y) * (w0.y*t10.y + w1.y*t11.y + w2.y*t12.y);
            r2.x = fast_silu(C[i][j][2] + bb.x) * (w0.x*t20.x + w1.x*t21.x + w2.x*t22.x);
            r2.y = fast_silu(C[i][j][3] + bb.y) * (w0.y*t20.y + w1.y*t21.y + w2.y*t22.y);
            *(float2*)(o1 + c0) = r1;
            *(float2*)(o2 + c0) = r2;
        }
    }
}

// ================= launch =================
extern "C" void kernel_launch(void* const* d_in, const int* in_sizes, int n_in,
                              void* d_out, int out_size)
{
    const float* x    = (const float*)d_in[0];
    const float* vec  = (const float*)d_in[1];
    const float* dist = (const float*)d_in[2];
    const float* edge = (const float*)d_in[3];
    const unsigned char* mraw = (const unsigned char*)d_in[4];
    const float* Wq   = (const float*)d_in[5];
    const float* bq   = (const float*)d_in[6];
    const float* Wk   = (const float*)d_in[7];
    const float* bk   = (const float*)d_in[8];
    const float* Wv   = (const float*)d_in[9];
    const float* bv   = (const float*)d_in[10];
    const float* Wdk  = (const float*)d_in[11];
    const float* bdk  = (const float*)d_in[12];
    const float* Wdu  = (const float*)d_in[13];
    const float* bdu  = (const float*)d_in[14];
    const float* Wdih = (const float*)d_in[15];
    const float* Wea  = (const float*)d_in[16];
    const float* bea  = (const float*)d_in[17];

    float* out_attn = (float*)d_out;                    // (B,N,D)
    float* out_ipe  = out_attn + Bb*Nn*Dd;              // (B,N,N,D)

    cudaFuncSetAttribute(fused_kernel, cudaFuncAttributeMaxDynamicSharedMemorySize, SMEM_BYTES);
    cudaFuncSetAttribute(ipe_kernel,   cudaFuncAttributeMaxDynamicSharedMemorySize, SMEM_BYTES);

    mask_conv_kernel<<<1, 256>>>(mraw);
    wconv_kernel<<<384, 256>>>(Wdk, Wdu, Wea);
    qkv_kernel<<<64, 256>>>(x, Wq, bq, Wk, bk, Wv, bv);
    fused_kernel<<<Bb*Nn, NTHREADS, SMEM_BYTES>>>(edge, dist, vec, bdk, bdu, out_attn);
    w_kernel<<<Bb*24, 256>>>(Wdih);
    ipe_kernel<<<Bb*Nn, NTHREADS, SMEM_BYTES>>>(edge, bea, out_ipe);
}

// round 11
// speedup vs baseline: 2.4669x; 1.0888x over previous
#include <cuda_runtime.h>
#include <cuda_bf16.h>
#include <cstdint>

#define Bb 8
#define Nn 96
#define Dd 256
#define CUTOFF 5.0f
#define PI_F 3.14159265358979f

// ================= scratch (device globals; no allocation allowed) =============
__device__ float gQ[Bb*Nn*Dd];
__device__ float gK[Bb*Nn*Dd];
__device__ float gV[Bb*Nn*Dd];
__device__ float gDU[Bb*Nn*3*Dd];
__device__ float gWS[Bb*Nn*3*Dd];
__device__ float gWT[Bb*Nn*3*Dd];
__device__ unsigned char gMask[Bb*Nn*Nn];
__device__ int gMode;
// Pre-converted weights: [mat: dk,du,ea][k-slice 0..7][32KB tile]
// Slice: [256 n][128B row: hi k0..31 in bytes 0..63 | lo k0..31 in bytes 64..127],
// 8-row atoms, XOR-swizzled (ldmatrix .col operand).
__device__ __align__(16) unsigned char gWB[3][8][32768];

// ================= helpers =================
__device__ __forceinline__ uint32_t smem_u32(const void* p) {
    uint32_t a;
    asm("{ .reg .u64 t; cvta.to.shared.u64 t, %1; cvt.u32.u64 %0, t; }" : "=r"(a) : "l"(p));
    return a;
}
__device__ __forceinline__ uint32_t swz(uint32_t b) { return b ^ ((b >> 3) & 0x70); }

// B slice byte offset: [256 n][32 k] bf16 + lo half, 128B rows, 8-row atoms
__device__ __forceinline__ uint32_t boff32(int n, int k, int lo) {
    uint32_t byte = ((n >> 3) << 10) + ((n & 7) << 7) + (lo << 6) + (k << 1);
    return swz(byte);
}
// A tile byte offset: [96 rows][256 cols] bf16, atoms 8r x 64c, 12 atom-rows per atom-col
__device__ __forceinline__ uint32_t a2_off(int row, int col) {
    uint32_t byte = (uint32_t)(((col >> 6) * 12 + (row >> 3)) << 10) + ((row & 7) << 7) + ((col & 63) << 1);
    return swz(byte);
}

__device__ __forceinline__ unsigned pack_bf2(float a, float b) {
    __nv_bfloat162 h = __floats2bfloat162_rn(a, b);
    return *reinterpret_cast<unsigned*>(&h);
}
__device__ __forceinline__ void split_bf(float x, float& hi, float& lo) {
    __nv_bfloat16 h = __float2bfloat16_rn(x);
    hi = __bfloat162float(h);
    lo = x - hi;
}

__device__ __forceinline__ void ldsm_x4(uint32_t& r0, uint32_t& r1, uint32_t& r2, uint32_t& r3, uint32_t addr) {
    asm volatile("ldmatrix.sync.aligned.m8n8.x4.shared.b16 {%0,%1,%2,%3}, [%4];"
                 : "=r"(r0), "=r"(r1), "=r"(r2), "=r"(r3) : "r"(addr));
}
__device__ __forceinline__ void mma16816(float* c, uint32_t a0, uint32_t a1, uint32_t a2, uint32_t a3,
                                         uint32_t b0, uint32_t b1) {
    asm volatile("mma.sync.aligned.m16n8k16.row.col.f32.bf16.bf16.f32 "
                 "{%0,%1,%2,%3}, {%4,%5,%6,%7}, {%8,%9}, {%0,%1,%2,%3};"
                 : "+f"(c[0]), "+f"(c[1]), "+f"(c[2]), "+f"(c[3])
                 : "r"(a0), "r"(a1), "r"(a2), "r"(a3), "r"(b0), "r"(b1));
}
__device__ __forceinline__ void cp16(uint32_t smem_addr, const void* gptr) {
    asm volatile("cp.async.cg.shared.global [%0], [%1], 16;" :: "r"(smem_addr), "l"(gptr));
}
#define CP_COMMIT() asm volatile("cp.async.commit_group;" ::: "memory")
#define CP_WAIT0()  asm volatile("cp.async.wait_group 0;" ::: "memory")
#define CP_WAIT1()  asm volatile("cp.async.wait_group 1;" ::: "memory")

// ================= FMA-only silu =================
__device__ __forceinline__ float fast_silu(float x) {
    float t = x * -1.4426950408889634f;
    t = fminf(fmaxf(t, -30.0f), 30.0f);
    float fn = rintf(t);
    float f  = t - fn;
    float p = 1.3333558e-3f;
    p = fmaf(p, f, 9.6181291e-3f);
    p = fmaf(p, f, 5.5504109e-2f);
    p = fmaf(p, f, 2.4022651e-1f);
    p = fmaf(p, f, 6.9314718e-1f);
    p = fmaf(p, f, 1.0f);
    float sc = __int_as_float(((int)fn + 127) << 23);
    float e = p * sc;
    float d = 1.0f + e;
    float y = __int_as_float(0x7EF311C3u - __float_as_int(d));
    y = y * (2.0f - d * y);
    y = y * (2.0f - d * y);
    y = y * (2.0f - d * y);
    return x * y;
}

// ================= mask dtype detect + apply (parallel) =================
__global__ void mask_detect_kernel(const unsigned char* __restrict__ raw) {
    __shared__ int ms;
    int tid = threadIdx.x;
    if (tid == 0) ms = 0;
    __syncthreads();
    int local = 0;
    const int NEL = Bb*Nn*Nn;
    for (int i = tid; i < NEL; i += 1024) {
        unsigned char bch = raw[i];
        if (bch != 0 && (i & 3) != 0) {
            if (bch == 0x80 || bch == 0x3F) local |= 2;
            else                            local |= 1;
        }
    }
    if (local) atomicOr(&ms, local);
    __syncthreads();
    if (tid == 0) gMode = ms;
}
__global__ void mask_apply_kernel(const unsigned char* __restrict__ raw) {
    int mode = gMode;
    int i = blockIdx.x * 1024 + threadIdx.x;   // 72*1024 == 73728 exactly
    unsigned char v;
    if (mode & 1)      v = (raw[i] != 0);
    else if (mode & 2) v = (((const float*)raw)[i] != 0.0f);
    else               v = (((const int*)raw)[i]   != 0);
    gMask[i] = v;
}

// ================= W pre-convert: W[k][n] fp32 -> interleaved hi|lo slices ====
__global__ __launch_bounds__(256) void wconv_kernel(
    const float* __restrict__ Wdk, const float* __restrict__ Wdu, const float* __restrict__ Wea)
{
    int idx = blockIdx.x * 256 + threadIdx.x;      // 3*256*128
    int mat = idx / (256*128);
    int rem = idx % (256*128);
    int n   = rem / 128;
    int kp  = rem % 128;
    int k0  = kp * 2;
    const float* W = (mat == 0) ? Wdk : (mat == 1) ? Wdu : Wea;
    float w0 = W[k0*Dd + n];
    float w1 = W[(k0+1)*Dd + n];
    float h0, l0, h1, l1;
    split_bf(w0, h0, l0);
    split_bf(w1, h1, l1);
    int slice = k0 >> 5;
    int kk = k0 & 31;
    *(unsigned*)(&gWB[mat][slice][boff32(n, kk, 0)]) = pack_bf2(h0, h1);
    *(unsigned*)(&gWB[mat][slice][boff32(n, kk, 1)]) = pack_bf2(l0, l1);
}

// ================= K0: Q/K/V = x @ W + b (SIMT, small) =================
__global__ __launch_bounds__(256) void qkv_kernel(
    const float* __restrict__ x,
    const float* __restrict__ Wq, const float* __restrict__ bq,
    const float* __restrict__ Wk, const float* __restrict__ bk,
    const float* __restrict__ Wv, const float* __restrict__ bv)
{
    __shared__ float xs[12][256];
    __shared__ float wch[32][256];
    int tid = threadIdx.x;
    int b   = blockIdx.x >> 3;
    int rg  = blockIdx.x & 7;
    int row0 = rg * 12;

    #pragma unroll
    for (int i = 0; i < 12; ++i)
        xs[i][tid] = x[(b*Nn + row0 + i)*Dd + tid];

    const float* Ws[3]  = {Wq, Wk, Wv};
    const float* bs[3]  = {bq, bk, bv};
    float*       os[3]  = {gQ, gK, gV};

    for (int w = 0; w < 3; ++w) {
        float acc[12];
        #pragma unroll
        for (int i = 0; i < 12; ++i) acc[i] = 0.f;
        const float* W = Ws[w];
        for (int ks = 0; ks < 8; ++ks) {
            __syncthreads();
            #pragma unroll
            for (int i = 0; i < 32; ++i)
                wch[i][tid] = W[(ks*32 + i)*Dd + tid];
            __syncthreads();
            #pragma unroll
            for (int kk = 0; kk < 32; kk += 4) {
                float w0 = wch[kk+0][tid], w1 = wch[kk+1][tid];
                float w2 = wch[kk+2][tid], w3 = wch[kk+3][tid];
                #pragma unroll
                for (int r = 0; r < 12; ++r) {
                    float4 xv = *(const float4*)&xs[r][ks*32 + kk];
                    acc[r] = fmaf(xv.x, w0, acc[r]);
                    acc[r] = fmaf(xv.y, w1, acc[r]);
                    acc[r] = fmaf(xv.z, w2, acc[r]);
                    acc[r] = fmaf(xv.w, w3, acc[r]);
                }
            }
        }
        float bias = bs[w][tid];
        #pragma unroll
        for (int r = 0; r < 12; ++r)
            os[w][(b*Nn + row0 + r)*Dd + tid] = acc[r] + bias;
        __syncthreads();
    }
}

// ================= smem layout (byte offsets after 1KB align) ======
#define A_HI 0
#define A_LO 49152
#define B0   98304
#define B1   131072
#define MISC 163840
#define SMEM_BYTES (1024 + 163840 + 8192)
#define NTHREADS 512

// convert 96x256 fp32 (global) -> A hi/lo bf16 swizzled tiles
__device__ __forceinline__ void convert_A(const float* __restrict__ src, char* smA_hi, char* smA_lo, int tid) {
    for (int idx = tid; idx < 96*32; idx += NTHREADS) {
        int row = idx >> 5;
        int c0  = (idx & 31) * 8;
        float4 e0 = *(const float4*)(src + row*Dd + c0);
        float4 e1 = *(const float4*)(src + row*Dd + c0 + 4);
        float h0,l0,h1,l1,h2,l2,h3,l3,h4,l4,h5,l5,h6,l6,h7,l7;
        split_bf(e0.x,h0,l0); split_bf(e0.y,h1,l1); split_bf(e0.z,h2,l2); split_bf(e0.w,h3,l3);
        split_bf(e1.x,h4,l4); split_bf(e1.y,h5,l5); split_bf(e1.z,h6,l6); split_bf(e1.w,h7,l7);
        uint32_t o = a2_off(row, c0);
        *(uint4*)(smA_hi + o) = make_uint4(pack_bf2(h0,h1), pack_bf2(h2,h3), pack_bf2(h4,h5), pack_bf2(h6,h7));
        *(uint4*)(smA_lo + o) = make_uint4(pack_bf2(l0,l1), pack_bf2(l2,l3), pack_bf2(l4,l5), pack_bf2(l6,l7));
    }
}

// async-stage one 32KB pre-swizzled B slice (hi|lo interleaved)
__device__ __forceinline__ void cp_slice(uint32_t smem_dst, const unsigned char* gsrc, int tid) {
    #pragma unroll
    for (int i = 0; i < 4; ++i) {
        int e = tid + NTHREADS*i;      // 2048 x 16B = 32KB
        cp16(smem_dst + e*16, gsrc + e*16);
    }
}

// one full 96x256x256 GEMM via HMMA, 3-term bf16 split.
// 8 k-slices of 32, double-buffered cp.async, single compute pass per slice.
// 16 warps: wg = w>>3 (m rows wg*48..+47, i<3), wn = w&7 (n cols wn*32..+31, j<4).
__device__ __forceinline__ void mma_gemm(int mat, uint32_t sb, int tid, float C[3][4][4]) {
    int lane = tid & 31;
    int w = tid >> 5;
    int wg = w >> 3;
    int n0 = (w & 7) * 32;
    int rowb = wg * 48;
    int aRow = (lane & 7) + 8 * ((lane >> 3) & 1);
    int aK   = 8 * (lane >> 4);
    int bMat = lane >> 3;
    int bRow = lane & 7;
    int bNo  = (bMat >> 1) * 8;
    int bKo  = (bMat & 1) * 8;

    #pragma unroll
    for (int i = 0; i < 3; ++i)
        #pragma unroll
        for (int j = 0; j < 4; ++j)
            #pragma unroll
            for (int q = 0; q < 4; ++q) C[i][j][q] = 0.f;

    // prologue: slice 0 -> B0
    cp_slice(sb + B0, gWB[mat][0], tid);
    CP_COMMIT();

    #pragma unroll 1
    for (int s = 0; s < 8; ++s) {
        uint32_t bufc = (s & 1) ? (sb + B1) : (sb + B0);
        uint32_t bufn = (s & 1) ? (sb + B0) : (sb + B1);
        if (s < 7) { cp_slice(bufn, gWB[mat][s+1], tid); CP_COMMIT(); CP_WAIT1(); }
        else       { CP_WAIT0(); }
        __syncthreads();

        #pragma unroll
        for (int t = 0; t < 2; ++t) {
            int k0 = t * 16;
            uint32_t bh[4][2], bl[4][2];
            #pragma unroll
            for (int jp = 0; jp < 2; ++jp) {
                int rn = n0 + jp*16 + bNo + bRow;
                ldsm_x4(bh[jp*2][0], bh[jp*2][1], bh[jp*2+1][0], bh[jp*2+1][1],
                        bufc + boff32(rn, k0 + bKo, 0));
                ldsm_x4(bl[jp*2][0], bl[jp*2][1], bl[jp*2+1][0], bl[jp*2+1][1],
                        bufc + boff32(rn, k0 + bKo, 1));
            }
            #pragma unroll
            for (int i = 0; i < 3; ++i) {
                uint32_t ao = a2_off(rowb + i*16 + aRow, s*32 + k0 + aK);
                uint32_t ah0,ah1,ah2,ah3, al0,al1,al2,al3;
                ldsm_x4(ah0,ah1,ah2,ah3, sb + A_HI + ao);
                ldsm_x4(al0,al1,al2,al3, sb + A_LO + ao);
                #pragma unroll
                for (int j = 0; j < 4; ++j) {
                    mma16816(C[i][j], ah0,ah1,ah2,ah3, bh[j][0], bh[j][1]);
                    mma16816(C[i][j], al0,al1,al2,al3, bh[j][0], bh[j][1]);
                    mma16816(C[i][j], ah0,ah1,ah2,ah3, bl[j][0], bl[j][1]);
                }
            }
        }
        __syncthreads();
    }
}

// ================= K1: fused dk-GEMM + attention + du-GEMM =================
__global__ __launch_bounds__(NTHREADS, 1) void fused_kernel(
    const float* __restrict__ edge,
    const float* __restrict__ dist,
    const float* __restrict__ vec,
    const float* __restrict__ bdk, const float* __restrict__ bdu,
    float* __restrict__ out_attn)
{
    extern __shared__ char smraw[];
    uint32_t sb0 = smem_u32(smraw);
    uint32_t alpad = (1024u - (sb0 & 1023u)) & 1023u;
    char* sm = smraw + alpad;
    uint32_t sb = sb0 + alpad;

    char* smA_hi = sm + A_HI;
    char* smA_lo = sm + A_LO;
    float* misc  = (float*)(sm + MISC);
    float* qs    = misc;            // 256
    float* b1s   = qs + 256;        // bdk
    float* b2s   = b1s + 256;       // bdu
    float* scl   = b2s + 256;       // 96
    float* mk    = scl + 96;        // 96
    float* vecs  = mk + 96;         // 288

    int tid = threadIdx.x;
    int lane = tid & 31;
    int w = tid >> 5;
    int wg = w >> 3;
    int g = lane >> 2, tig = lane & 3;
    int n0 = (w & 7) * 32;
    int rowb = wg * 48;
    int b = blockIdx.x / Nn;
    int n = blockIdx.x % Nn;
    int bO = b * Nn;

    if (tid < 256) {
        qs[tid]  = gQ[(bO + n)*Dd + tid];
        b1s[tid] = bdk[tid];
        b2s[tid] = bdu[tid];
    }
    if (tid < 96) {
        unsigned char mm = gMask[(bO + n)*Nn + tid];
        float dd = dist[(bO + n)*Nn + tid];
        float cs = (dd < CUTOFF) ? 0.5f*(cosf(dd*(PI_F/CUTOFF)) + 1.f) : 0.f;
        scl[tid] = mm ? 0.f : cs;
        mk[tid]  = mm ? 0.f : 1.f;
    }
    if (tid < 288) vecs[tid] = vec[(size_t)(bO + n)*Nn*3 + tid];

    convert_A(edge + (size_t)(bO + n)*Nn*Dd, smA_hi, smA_lo, tid);
    __syncthreads();

    float C[3][4][4];

    // ---------- GEMM1: dk preact ----------
    mma_gemm(0, sb, tid, C);

    // ---------- epilogue 1: silu + attn weights + probs + As ----------
    #pragma unroll
    for (int i = 0; i < 3; ++i) {
        int m1 = rowb + i*16 + g, m2 = m1 + 8;
        float t1 = 0.f, t2 = 0.f;
        #pragma unroll
        for (int j = 0; j < 4; ++j) {
            int c0 = n0 + j*8 + tig*2;
            float bb0 = b1s[c0], bb1 = b1s[c0+1];
            float q0 = qs[c0], q1 = qs[c0+1];
            float d0 = fast_silu(C[i][j][0] + bb0);
            float d1 = fast_silu(C[i][j][1] + bb1);
            float d2 = fast_silu(C[i][j][2] + bb0);
            float d3 = fast_silu(C[i][j][3] + bb1);
            float2 k1v = *(const float2*)&gK[(size_t)(bO + m1)*Dd + c0];
            float2 k2v = *(const float2*)&gK[(size_t)(bO + m2)*Dd + c0];
            t1 = fmaf(d0, q0*k1v.x, fmaf(d1, q1*k1v.y, t1));
            t2 = fmaf(d2, q0*k2v.x, fmaf(d3, q1*k2v.y, t2));
        }
        t1 += __shfl_xor_sync(0xffffffffu, t1, 1);
        t1 += __shfl_xor_sync(0xffffffffu, t1, 2);
        t2 += __shfl_xor_sync(0xffffffffu, t2, 1);
        t2 += __shfl_xor_sync(0xffffffffu, t2, 2);
        float p1 = fast_silu(t1) * scl[m1];
        float p2 = fast_silu(t2) * scl[m2];
        #pragma unroll
        for (int j = 0; j < 4; ++j) {
            int c0 = n0 + j*8 + tig*2;
            float2 v1 = *(const float2*)&gV[(size_t)(bO + m1)*Dd + c0];
            float2 v2 = *(const float2*)&gV[(size_t)(bO + m2)*Dd + c0];
            float a0 = p1*v1.x, a1 = p1*v1.y, a2 = p2*v2.x, a3 = p2*v2.y;
            float h0,l0,h1,l1,h2,l2,h3,l3;
            split_bf(a0,h0,l0); split_bf(a1,h1,l1);
            split_bf(a2,h2,l2); split_bf(a3,h3,l3);
            *(unsigned*)(smA_hi + a2_off(m1, c0)) = pack_bf2(h0,h1);
            *(unsigned*)(smA_lo + a2_off(m1, c0)) = pack_bf2(l0,l1);
            *(unsigned*)(smA_hi + a2_off(m2, c0)) = pack_bf2(h2,h3);
            *(unsigned*)(smA_lo + a2_off(m2, c0)) = pack_bf2(l2,l3);
        }
    }
    __syncthreads();

    // ---------- attn = column sums of As ----------
    if (tid < 256) {
        float s = 0.f;
        #pragma unroll 4
        for (int m = 0; m < 96; ++m) {
            uint32_t o = a2_off(m, tid);
            float hv = __bfloat162float(*(const __nv_bfloat16*)(smA_hi + o));
            float lv = __bfloat162float(*(const __nv_bfloat16*)(smA_lo + o));
            s += hv + lv;
        }
        out_attn[(bO + n)*Dd + tid] = s;
    }
    __syncthreads();

    // ---------- GEMM2: du_in = As @ Wdu ----------
    mma_gemm(1, sb, tid, C);

    // ---------- epilogue 2: din = (C + bdu)*keep -> fp32 plane (reuse A region) ----------
    float* din = (float*)(sm + A_HI);   // [96][256] fp32 = 96KB
    #pragma unroll
    for (int i = 0; i < 3; ++i) {
        int m1 = rowb + i*16 + g, m2 = m1 + 8;
        float k1 = mk[m1], k2 = mk[m2];
        #pragma unroll
        for (int j = 0; j < 4; ++j) {
            int c0 = n0 + j*8 + tig*2;
            float2 d1 = make_float2((C[i][j][0] + b2s[c0]) * k1, (C[i][j][1] + b2s[c0+1]) * k1);
            float2 d2 = make_float2((C[i][j][2] + b2s[c0]) * k2, (C[i][j][3] + b2s[c0+1]) * k2);
            *(float2*)&din[m1*Dd + c0] = d1;
            *(float2*)&din[m2*Dd + c0] = d2;
        }
    }
    __syncthreads();

    // ---------- du[comp][c] = sum_m din[m][c] * vec[m][comp] ----------
    if (tid < 256) {
        float a0 = 0.f, a1 = 0.f, a2 = 0.f;
        #pragma unroll 4
        for (int m = 0; m < 96; ++m) {
            float v = din[m*Dd + tid];
            a0 = fmaf(v, vecs[m*3+0], a0);
            a1 = fmaf(v, vecs[m*3+1], a1);
            a2 = fmaf(v, vecs[m*3+2], a2);
        }
        gDU[((bO + n)*3 + 0)*Dd + tid] = a0;
        gDU[((bO + n)*3 + 1)*Dd + tid] = a1;
        gDU[((bO + n)*3 + 2)*Dd + tid] = a2;
    }
}

// ================= K2: w = du @ Wdih (SIMT, cp.async double-buffered) ============
#define WSMEM_BYTES (12288 + 2*32768)
__global__ __launch_bounds__(256) void w_kernel(const float* __restrict__ Wdih)
{
    extern __shared__ float wsm[];
    float* dus  = wsm;                 // 12*256
    float* wch0 = wsm + 3072;          // 16*512
    float* wch1 = wch0 + 8192;
    uint32_t sbw = smem_u32(wsm);
    uint32_t a_wch0 = sbw + 3072*4;
    uint32_t a_wch1 = a_wch0 + 8192*4;

    int tid = threadIdx.x;
    int b  = blockIdx.x / 24;
    int ng = blockIdx.x % 24;
    int nbase = ng * 4;

    // prefetch ks=0
    {
        const char* gsrc = (const char*)Wdih;
        #pragma unroll
        for (int i = 0; i < 8; ++i) {
            int e = tid + 256*i;
            cp16(a_wch0 + e*16, gsrc + e*16);
        }
        CP_COMMIT();
    }

    size_t dbase = (size_t)(b*Nn + nbase) * 3 * Dd;
    #pragma unroll
    for (int i = 0; i < 12; ++i)
        dus[tid + 256*i] = gDU[dbase + tid + 256*i];

    float acc0[12], acc1[12];
    #pragma unroll
    for (int q = 0; q < 12; ++q) { acc0[q] = 0.f; acc1[q] = 0.f; }

    #pragma unroll 1
    for (int ks = 0; ks < 16; ++ks) {
        uint32_t a_next = (ks & 1) ? a_wch0 : a_wch1;
        const float* wchc = (ks & 1) ? wch1 : wch0;
        if (ks < 15) {
            const char* gsrc = (const char*)(Wdih + (size_t)(ks+1)*16*512);
            #pragma unroll
            for (int i = 0; i < 8; ++i) {
                int e = tid + 256*i;
                cp16(a_next + e*16, gsrc + e*16);
            }
            CP_COMMIT(); CP_WAIT1();
        } else {
            CP_WAIT0();
        }
        __syncthreads();
        #pragma unroll
        for (int kk = 0; kk < 16; ++kk) {
            float w0 = wchc[kk*512 + tid];
            float w1 = wchc[kk*512 + 256 + tid];
            #pragma unroll
            for (int q = 0; q < 12; ++q) {
                float xv = dus[q*256 + ks*16 + kk];
                acc0[q] = fmaf(xv, w0, acc0[q]);
                acc1[q] = fmaf(xv, w1, acc1[q]);
            }
        }
        __syncthreads();
    }
    #pragma unroll
    for (int q = 0; q < 12; ++q) {
        int ni = q / 3, c = q % 3;
        gWS[((b*Nn + nbase + ni)*3 + c)*Dd + tid] = acc0[q];
        gWT[((b*Nn + nbase + ni)*3 + c)*Dd + tid] = acc1[q];
    }
}

// ================= K3: ipe = silu(E @ Wea + bea) * (ws . wt) =================
__global__ __launch_bounds__(NTHREADS, 1) void ipe_kernel(
    const float* __restrict__ edge,
    const float* __restrict__ bea,
    float* __restrict__ out_ipe)
{
    extern __shared__ char smraw[];
    uint32_t sb0 = smem_u32(smraw);
    uint32_t alpad = (1024u - (sb0 & 1023u)) & 1023u;
    char* sm = smraw + alpad;
    uint32_t sb = sb0 + alpad;

    char* smA_hi = sm + A_HI;
    char* smA_lo = sm + A_LO;
    float* misc  = (float*)(sm + MISC);
    float* bs    = misc;            // 256
    float* wsr   = bs + 256;        // 3x256

    int tid = threadIdx.x;
    int lane = tid & 31;
    int w = tid >> 5;
    int wg = w >> 3;
    int g = lane >> 2, tig = lane & 3;
    int n0 = (w & 7) * 32;
    int rowb = wg * 48;
    int b = blockIdx.x / Nn;
    int n = blockIdx.x % Nn;
    int bO = b * Nn;

    if (tid < 256) {
        bs[tid] = bea[tid];
        size_t wbase = (size_t)(bO + n) * 3 * Dd;
        #pragma unroll
        for (int i = 0; i < 3; ++i) wsr[i*256 + tid] = gWS[wbase + i*256 + tid];
    }
    convert_A(edge + (size_t)(bO + n)*Nn*Dd, smA_hi, smA_lo, tid);
    __syncthreads();

    float C[3][4][4];
    mma_gemm(2, sb, tid, C);

    #pragma unroll
    for (int i = 0; i < 3; ++i) {
        int m1 = rowb + i*16 + g, m2 = m1 + 8;
        const float* wt1 = &gWT[(size_t)((bO + m1)*3)*Dd];
        const float* wt2 = &gWT[(size_t)((bO + m2)*3)*Dd];
        float* o1 = &out_ipe[((size_t)(bO + n)*Nn + m1)*Dd];
        float* o2 = &out_ipe[((size_t)(bO + n)*Nn + m2)*Dd];
        #pragma unroll
        for (int j = 0; j < 4; ++j) {
            int c0 = n0 + j*8 + tig*2;
            float2 w0 = *(const float2*)&wsr[0*256 + c0];
            float2 w1 = *(const float2*)&wsr[1*256 + c0];
            float2 w2 = *(const float2*)&wsr[2*256 + c0];
            float2 bb = *(const float2*)&bs[c0];
            float2 t10 = *(const float2*)(wt1 + c0);
            float2 t11 = *(const float2*)(wt1 + 256 + c0);
            float2 t12 = *(const float2*)(wt1 + 512 + c0);
            float2 t20 = *(const float2*)(wt2 + c0);
            float2 t21 = *(const float2*)(wt2 + 256 + c0);
            float2 t22 = *(const float2*)(wt2 + 512 + c0);
            float2 r1, r2;
            r1.x = fast_silu(C[i][j][0] + bb.x) * (w0.x*t10.x + w1.x*t11.x + w2.x*t12.x);
            r1.y = fast_silu(C[i][j][1] + bb.y) * (w0.y*t10.y + w1.y*t11.y + w2.y*t12.y);
            r2.x = fast_silu(C[i][j][2] + bb.x) * (w0.x*t20.x + w1.x*t21.x + w2.x*t22.x);
            r2.y = fast_silu(C[i][j][3] + bb.y) * (w0.y*t20.y + w1.y*t21.y + w2.y*t22.y);
            *(float2*)(o1 + c0) = r1;
            *(float2*)(o2 + c0) = r2;
        }
    }
}

// ================= launch =================
extern "C" void kernel_launch(void* const* d_in, const int* in_sizes, int n_in,
                              void* d_out, int out_size)
{
    const float* x    = (const float*)d_in[0];
    const float* vec  = (const float*)d_in[1];
    const float* dist = (const float*)d_in[2];
    const float* edge = (const float*)d_in[3];
    const unsigned char* mraw = (const unsigned char*)d_in[4];
    const float* Wq   = (const float*)d_in[5];
    const float* bq   = (const float*)d_in[6];
    const float* Wk   = (const float*)d_in[7];
    const float* bk   = (const float*)d_in[8];
    const float* Wv   = (const float*)d_in[9];
    const float* bv   = (const float*)d_in[10];
    const float* Wdk  = (const float*)d_in[11];
    const float* bdk  = (const float*)d_in[12];
    const float* Wdu  = (const float*)d_in[13];
    const float* bdu  = (const float*)d_in[14];
    const float* Wdih = (const float*)d_in[15];
    const float* Wea  = (const float*)d_in[16];
    const float* bea  = (const float*)d_in[17];

    float* out_attn = (float*)d_out;                    // (B,N,D)
    float* out_ipe  = out_attn + Bb*Nn*Dd;              // (B,N,N,D)

    cudaFuncSetAttribute(fused_kernel, cudaFuncAttributeMaxDynamicSharedMemorySize, SMEM_BYTES);
    cudaFuncSetAttribute(ipe_kernel,   cudaFuncAttributeMaxDynamicSharedMemorySize, SMEM_BYTES);
    cudaFuncSetAttribute(w_kernel,     cudaFuncAttributeMaxDynamicSharedMemorySize, WSMEM_BYTES);

    mask_detect_kernel<<<1, 1024>>>(mraw);
    mask_apply_kernel<<<72, 1024>>>(mraw);
    wconv_kernel<<<384, 256>>>(Wdk, Wdu, Wea);
    qkv_kernel<<<64, 256>>>(x, Wq, bq, Wk, bk, Wv, bv);
    fused_kernel<<<Bb*Nn, NTHREADS, SMEM_BYTES>>>(edge, dist, vec, bdk, bdu, out_attn);
    w_kernel<<<Bb*24, 256, WSMEM_BYTES>>>(Wdih);
    ipe_kernel<<<Bb*Nn, NTHREADS, SMEM_BYTES>>>(edge, bea, out_ipe);
}

// round 15
// speedup vs baseline: 3.9374x; 1.5961x over previous
#include <cuda_runtime.h>
#include <cuda_bf16.h>
#include <cstdint>

#define Bb 8
#define Nn 96
#define Dd 256
#define CUTOFF 5.0f
#define PI_F 3.14159265358979f

// ================= scratch (device globals; no allocation allowed) =============
__device__ float gQ[Bb*Nn*Dd];
__device__ float gK[Bb*Nn*Dd];
__device__ float gV[Bb*Nn*Dd];
__device__ float gDU[Bb*Nn*3*Dd];
__device__ float gWS[Bb*Nn*3*Dd];
__device__ float gWT[Bb*Nn*3*Dd];
__device__ unsigned char gMask[Bb*Nn*Nn];
__device__ int gMode;
// Pre-converted weights: [mat: dk,du,ea][k-slice 0..7][32KB tile]
// Slice: [256 n][128B row: hi k0..31 in bytes 0..63 | lo k0..31 in bytes 64..127],
// 8-row atoms, XOR-swizzled (ldmatrix .col operand).
__device__ __align__(16) unsigned char gWB[3][8][32768];

// ================= helpers =================
__device__ __forceinline__ uint32_t smem_u32(const void* p) {
    uint32_t a;
    asm("{ .reg .u64 t; cvta.to.shared.u64 t, %1; cvt.u32.u64 %0, t; }" : "=r"(a) : "l"(p));
    return a;
}
__device__ __forceinline__ uint32_t swz(uint32_t b) { return b ^ ((b >> 3) & 0x70); }

// B slice byte offset: [256 n][32 k] bf16 + lo half, 128B rows, 8-row atoms
__device__ __forceinline__ uint32_t boff32(int n, int k, int lo) {
    uint32_t byte = ((n >> 3) << 10) + ((n & 7) << 7) + (lo << 6) + (k << 1);
    return swz(byte);
}
// A tile byte offset: [96 rows][256 cols] bf16, atoms 8r x 64c, 12 atom-rows per atom-col
__device__ __forceinline__ uint32_t a2_off(int row, int col) {
    uint32_t byte = (uint32_t)(((col >> 6) * 12 + (row >> 3)) << 10) + ((row & 7) << 7) + ((col & 63) << 1);
    return swz(byte);
}

__device__ __forceinline__ unsigned pack_bf2(float a, float b) {
    __nv_bfloat162 h = __floats2bfloat162_rn(a, b);
    return *reinterpret_cast<unsigned*>(&h);
}
__device__ __forceinline__ void split_bf(float x, float& hi, float& lo) {
    __nv_bfloat16 h = __float2bfloat16_rn(x);
    hi = __bfloat162float(h);
    lo = x - hi;
}

__device__ __forceinline__ void ldsm_x4(uint32_t& r0, uint32_t& r1, uint32_t& r2, uint32_t& r3, uint32_t addr) {
    asm volatile("ldmatrix.sync.aligned.m8n8.x4.shared.b16 {%0,%1,%2,%3}, [%4];"
                 : "=r"(r0), "=r"(r1), "=r"(r2), "=r"(r3) : "r"(addr));
}
__device__ __forceinline__ void mma16816(float* c, uint32_t a0, uint32_t a1, uint32_t a2, uint32_t a3,
                                         uint32_t b0, uint32_t b1) {
    asm volatile("mma.sync.aligned.m16n8k16.row.col.f32.bf16.bf16.f32 "
                 "{%0,%1,%2,%3}, {%4,%5,%6,%7}, {%8,%9}, {%0,%1,%2,%3};"
                 : "+f"(c[0]), "+f"(c[1]), "+f"(c[2]), "+f"(c[3])
                 : "r"(a0), "r"(a1), "r"(a2), "r"(a3), "r"(b0), "r"(b1));
}
__device__ __forceinline__ void cp16(uint32_t smem_addr, const void* gptr) {
    asm volatile("cp.async.cg.shared.global [%0], [%1], 16;" :: "r"(smem_addr), "l"(gptr));
}
#define CP_COMMIT() asm volatile("cp.async.commit_group;" ::: "memory")
#define CP_WAIT0()  asm volatile("cp.async.wait_group 0;" ::: "memory")
#define CP_WAIT1()  asm volatile("cp.async.wait_group 1;" ::: "memory")

// ================= FMA-only silu =================
__device__ __forceinline__ float fast_silu(float x) {
    float t = x * -1.4426950408889634f;
    t = fminf(fmaxf(t, -30.0f), 30.0f);
    float fn = rintf(t);
    float f  = t - fn;
    float p = 1.3333558e-3f;
    p = fmaf(p, f, 9.6181291e-3f);
    p = fmaf(p, f, 5.5504109e-2f);
    p = fmaf(p, f, 2.4022651e-1f);
    p = fmaf(p, f, 6.9314718e-1f);
    p = fmaf(p, f, 1.0f);
    float sc = __int_as_float(((int)fn + 127) << 23);
    float e = p * sc;
    float d = 1.0f + e;
    float y = __int_as_float(0x7EF311C3u - __float_as_int(d));
    y = y * (2.0f - d * y);
    y = y * (2.0f - d * y);
    y = y * (2.0f - d * y);
    return x * y;
}

// ================= mask dtype detect + apply (parallel) =================
__global__ void mask_detect_kernel(const unsigned char* __restrict__ raw) {
    __shared__ int ms;
    int tid = threadIdx.x;
    if (tid == 0) ms = 0;
    __syncthreads();
    int local = 0;
    const int NEL = Bb*Nn*Nn;
    for (int i = tid; i < NEL; i += 1024) {
        unsigned char bch = raw[i];
        if (bch != 0 && (i & 3) != 0) {
            if (bch == 0x80 || bch == 0x3F) local |= 2;
            else                            local |= 1;
        }
    }
    if (local) atomicOr(&ms, local);
    __syncthreads();
    if (tid == 0) gMode = ms;
}
__global__ void mask_apply_kernel(const unsigned char* __restrict__ raw) {
    int mode = gMode;
    int i = blockIdx.x * 1024 + threadIdx.x;   // 72*1024 == 73728 exactly
    unsigned char v;
    if (mode & 1)      v = (raw[i] != 0);
    else if (mode & 2) v = (((const float*)raw)[i] != 0.0f);
    else               v = (((const int*)raw)[i]   != 0);
    gMask[i] = v;
}

// ================= W pre-convert: W[k][n] fp32 -> interleaved hi|lo slices ====
__global__ __launch_bounds__(256) void wconv_kernel(
    const float* __restrict__ Wdk, const float* __restrict__ Wdu, const float* __restrict__ Wea)
{
    int idx = blockIdx.x * 256 + threadIdx.x;      // 3*256*128
    int mat = idx / (256*128);
    int rem = idx % (256*128);
    int n   = rem / 128;
    int kp  = rem % 128;
    int k0  = kp * 2;
    const float* W = (mat == 0) ? Wdk : (mat == 1) ? Wdu : Wea;
    float w0 = W[k0*Dd + n];
    float w1 = W[(k0+1)*Dd + n];
    float h0, l0, h1, l1;
    split_bf(w0, h0, l0);
    split_bf(w1, h1, l1);
    int slice = k0 >> 5;
    int kk = k0 & 31;
    *(unsigned*)(&gWB[mat][slice][boff32(n, kk, 0)]) = pack_bf2(h0, h1);
    *(unsigned*)(&gWB[mat][slice][boff32(n, kk, 1)]) = pack_bf2(l0, l1);
}

// ================= K0: Q/K/V = x @ W + b (cp.async pipelined, 192 blocks) =========
// grid: b(8) x rg(8) x mat(3). Each block: 12 x-rows, one weight matrix,
// 8 k-chunks of 32x256 floats double-buffered via cp.async.
#define QKV_SMEM_BYTES (12288 + 2*32768)
__global__ __launch_bounds__(256) void qkv_kernel(
    const float* __restrict__ x,
    const float* __restrict__ Wq, const float* __restrict__ bq,
    const float* __restrict__ Wk, const float* __restrict__ bk,
    const float* __restrict__ Wv, const float* __restrict__ bv)
{
    extern __shared__ float qsm[];
    float* xs   = qsm;                 // 12*256
    float* wch0 = qsm + 3072;          // 32*256
    float* wch1 = wch0 + 8192;
    uint32_t sbq = smem_u32(qsm);
    uint32_t a_wch0 = sbq + 3072*4;
    uint32_t a_wch1 = a_wch0 + 8192*4;

    int tid  = threadIdx.x;
    int blk  = blockIdx.x;
    int wsel = blk % 3;
    int rg   = (blk / 3) & 7;
    int b    = blk / 24;
    int row0 = rg * 12;

    const float* W    = (wsel == 0) ? Wq : (wsel == 1) ? Wk : Wv;
    const float* bias = (wsel == 0) ? bq : (wsel == 1) ? bk : bv;
    float* out        = (wsel == 0) ? gQ : (wsel == 1) ? gK : gV;

    // prefetch chunk 0
    {
        const char* gsrc = (const char*)W;
        #pragma unroll
        for (int i = 0; i < 8; ++i) {
            int e = tid + 256*i;       // 2048 x 16B = 32KB
            cp16(a_wch0 + e*16, gsrc + e*16);
        }
        CP_COMMIT();
    }

    #pragma unroll
    for (int i = 0; i < 12; ++i)
        xs[i*256 + tid] = x[(b*Nn + row0 + i)*Dd + tid];

    float acc[12];
    #pragma unroll
    for (int i = 0; i < 12; ++i) acc[i] = 0.f;

    #pragma unroll 1
    for (int ks = 0; ks < 8; ++ks) {
        uint32_t a_next = (ks & 1) ? a_wch0 : a_wch1;
        const float* wchc = (ks & 1) ? wch1 : wch0;
        if (ks < 7) {
            const char* gsrc = (const char*)(W + (size_t)(ks+1)*32*Dd);
            #pragma unroll
            for (int i = 0; i < 8; ++i) {
                int e = tid + 256*i;
                cp16(a_next + e*16, gsrc + e*16);
            }
            CP_COMMIT(); CP_WAIT1();
        } else {
            CP_WAIT0();
        }
        __syncthreads();
        #pragma unroll
        for (int kk = 0; kk < 32; kk += 4) {
            float w0 = wchc[(kk+0)*256 + tid], w1 = wchc[(kk+1)*256 + tid];
            float w2 = wchc[(kk+2)*256 + tid], w3 = wchc[(kk+3)*256 + tid];
            #pragma unroll
            for (int r = 0; r < 12; ++r) {
                float4 xv = *(const float4*)&xs[r*256 + ks*32 + kk];
                acc[r] = fmaf(xv.x, w0, acc[r]);
                acc[r] = fmaf(xv.y, w1, acc[r]);
                acc[r] = fmaf(xv.z, w2, acc[r]);
                acc[r] = fmaf(xv.w, w3, acc[r]);
            }
        }
        __syncthreads();
    }
    float bb = bias[tid];
    #pragma unroll
    for (int r = 0; r < 12; ++r)
        out[(b*Nn + row0 + r)*Dd + tid] = acc[r] + bb;
}

// ================= smem layout (byte offsets after 1KB align) ======
#define A_HI 0
#define A_LO 49152
#define B0   98304
#define B1   131072
#define MISC 163840
#define SMEM_BYTES (1024 + 163840 + 8192)
#define NTHREADS 512

// convert 96x256 fp32 (global) -> A hi/lo bf16 swizzled tiles
__device__ __forceinline__ void convert_A(const float* __restrict__ src, char* smA_hi, char* smA_lo, int tid) {
    for (int idx = tid; idx < 96*32; idx += NTHREADS) {
        int row = idx >> 5;
        int c0  = (idx & 31) * 8;
        float4 e0 = *(const float4*)(src + row*Dd + c0);
        float4 e1 = *(const float4*)(src + row*Dd + c0 + 4);
        float h0,l0,h1,l1,h2,l2,h3,l3,h4,l4,h5,l5,h6,l6,h7,l7;
        split_bf(e0.x,h0,l0); split_bf(e0.y,h1,l1); split_bf(e0.z,h2,l2); split_bf(e0.w,h3,l3);
        split_bf(e1.x,h4,l4); split_bf(e1.y,h5,l5); split_bf(e1.z,h6,l6); split_bf(e1.w,h7,l7);
        uint32_t o = a2_off(row, c0);
        *(uint4*)(smA_hi + o) = make_uint4(pack_bf2(h0,h1), pack_bf2(h2,h3), pack_bf2(h4,h5), pack_bf2(h6,h7));
        *(uint4*)(smA_lo + o) = make_uint4(pack_bf2(l0,l1), pack_bf2(l2,l3), pack_bf2(l4,l5), pack_bf2(l6,l7));
    }
}

// async-stage one 32KB pre-swizzled B slice (hi|lo interleaved)
__device__ __forceinline__ void cp_slice(uint32_t smem_dst, const unsigned char* gsrc, int tid) {
    #pragma unroll
    for (int i = 0; i < 4; ++i) {
        int e = tid + NTHREADS*i;      // 2048 x 16B = 32KB
        cp16(smem_dst + e*16, gsrc + e*16);
    }
}

// one full 96x256x256 GEMM via HMMA, 3-term bf16 split.
// 8 k-slices of 32, double-buffered cp.async, single compute pass per slice.
// 16 warps: wg = w>>3 (m rows wg*48..+47, i<3), wn = w&7 (n cols wn*32..+31, j<4).
__device__ __forceinline__ void mma_gemm(int mat, uint32_t sb, int tid, float C[3][4][4]) {
    int lane = tid & 31;
    int w = tid >> 5;
    int wg = w >> 3;
    int n0 = (w & 7) * 32;
    int rowb = wg * 48;
    int aRow = (lane & 7) + 8 * ((lane >> 3) & 1);
    int aK   = 8 * (lane >> 4);
    int bMat = lane >> 3;
    int bRow = lane & 7;
    int bNo  = (bMat >> 1) * 8;
    int bKo  = (bMat & 1) * 8;

    #pragma unroll
    for (int i = 0; i < 3; ++i)
        #pragma unroll
        for (int j = 0; j < 4; ++j)
            #pragma unroll
            for (int q = 0; q < 4; ++q) C[i][j][q] = 0.f;

    // prologue: slice 0 -> B0
    cp_slice(sb + B0, gWB[mat][0], tid);
    CP_COMMIT();

    #pragma unroll 1
    for (int s = 0; s < 8; ++s) {
        uint32_t bufc = (s & 1) ? (sb + B1) : (sb + B0);
        uint32_t bufn = (s & 1) ? (sb + B0) : (sb + B1);
        if (s < 7) { cp_slice(bufn, gWB[mat][s+1], tid); CP_COMMIT(); CP_WAIT1(); }
        else       { CP_WAIT0(); }
        __syncthreads();

        #pragma unroll
        for (int t = 0; t < 2; ++t) {
            int k0 = t * 16;
            uint32_t bh[4][2], bl[4][2];
            #pragma unroll
            for (int jp = 0; jp < 2; ++jp) {
                int rn = n0 + jp*16 + bNo + bRow;
                ldsm_x4(bh[jp*2][0], bh[jp*2][1], bh[jp*2+1][0], bh[jp*2+1][1],
                        bufc + boff32(rn, k0 + bKo, 0));
                ldsm_x4(bl[jp*2][0], bl[jp*2][1], bl[jp*2+1][0], bl[jp*2+1][1],
                        bufc + boff32(rn, k0 + bKo, 1));
            }
            #pragma unroll
            for (int i = 0; i < 3; ++i) {
                uint32_t ao = a2_off(rowb + i*16 + aRow, s*32 + k0 + aK);
                uint32_t ah0,ah1,ah2,ah3, al0,al1,al2,al3;
                ldsm_x4(ah0,ah1,ah2,ah3, sb + A_HI + ao);
                ldsm_x4(al0,al1,al2,al3, sb + A_LO + ao);
                #pragma unroll
                for (int j = 0; j < 4; ++j) {
                    mma16816(C[i][j], ah0,ah1,ah2,ah3, bh[j][0], bh[j][1]);
                    mma16816(C[i][j], al0,al1,al2,al3, bh[j][0], bh[j][1]);
                    mma16816(C[i][j], ah0,ah1,ah2,ah3, bl[j][0], bl[j][1]);
                }
            }
        }
        __syncthreads();
    }
}

// ================= K1: fused dk-GEMM + attention + du-GEMM =================
__global__ __launch_bounds__(NTHREADS, 1) void fused_kernel(
    const float* __restrict__ edge,
    const float* __restrict__ dist,
    const float* __restrict__ vec,
    const float* __restrict__ bdk, const float* __restrict__ bdu,
    float* __restrict__ out_attn)
{
    extern __shared__ char smraw[];
    uint32_t sb0 = smem_u32(smraw);
    uint32_t alpad = (1024u - (sb0 & 1023u)) & 1023u;
    char* sm = smraw + alpad;
    uint32_t sb = sb0 + alpad;

    char* smA_hi = sm + A_HI;
    char* smA_lo = sm + A_LO;
    float* misc  = (float*)(sm + MISC);
    float* qs    = misc;            // 256
    float* b1s   = qs + 256;        // bdk
    float* b2s   = b1s + 256;       // bdu
    float* scl   = b2s + 256;       // 96
    float* mk    = scl + 96;        // 96
    float* vecs  = mk + 96;         // 288

    int tid = threadIdx.x;
    int lane = tid & 31;
    int w = tid >> 5;
    int wg = w >> 3;
    int g = lane >> 2, tig = lane & 3;
    int n0 = (w & 7) * 32;
    int rowb = wg * 48;
    int b = blockIdx.x / Nn;
    int n = blockIdx.x % Nn;
    int bO = b * Nn;

    if (tid < 256) {
        qs[tid]  = gQ[(bO + n)*Dd + tid];
        b1s[tid] = bdk[tid];
        b2s[tid] = bdu[tid];
    }
    if (tid < 96) {
        unsigned char mm = gMask[(bO + n)*Nn + tid];
        float dd = dist[(bO + n)*Nn + tid];
        float cs = (dd < CUTOFF) ? 0.5f*(cosf(dd*(PI_F/CUTOFF)) + 1.f) : 0.f;
        scl[tid] = mm ? 0.f : cs;
        mk[tid]  = mm ? 0.f : 1.f;
    }
    if (tid < 288) vecs[tid] = vec[(size_t)(bO + n)*Nn*3 + tid];

    convert_A(edge + (size_t)(bO + n)*Nn*Dd, smA_hi, smA_lo, tid);
    __syncthreads();

    float C[3][4][4];

    // ---------- GEMM1: dk preact ----------
    mma_gemm(0, sb, tid, C);

    // ---------- epilogue 1: silu + attn weights + probs + As ----------
    #pragma unroll
    for (int i = 0; i < 3; ++i) {
        int m1 = rowb + i*16 + g, m2 = m1 + 8;
        float t1 = 0.f, t2 = 0.f;
        #pragma unroll
        for (int j = 0; j < 4; ++j) {
            int c0 = n0 + j*8 + tig*2;
            float bb0 = b1s[c0], bb1 = b1s[c0+1];
            float q0 = qs[c0], q1 = qs[c0+1];
            float d0 = fast_silu(C[i][j][0] + bb0);
            float d1 = fast_silu(C[i][j][1] + bb1);
            float d2 = fast_silu(C[i][j][2] + bb0);
            float d3 = fast_silu(C[i][j][3] + bb1);
            float2 k1v = *(const float2*)&gK[(size_t)(bO + m1)*Dd + c0];
            float2 k2v = *(const float2*)&gK[(size_t)(bO + m2)*Dd + c0];
            t1 = fmaf(d0, q0*k1v.x, fmaf(d1, q1*k1v.y, t1));
            t2 = fmaf(d2, q0*k2v.x, fmaf(d3, q1*k2v.y, t2));
        }
        t1 += __shfl_xor_sync(0xffffffffu, t1, 1);
        t1 += __shfl_xor_sync(0xffffffffu, t1, 2);
        t2 += __shfl_xor_sync(0xffffffffu, t2, 1);
        t2 += __shfl_xor_sync(0xffffffffu, t2, 2);
        float p1 = fast_silu(t1) * scl[m1];
        float p2 = fast_silu(t2) * scl[m2];
        #pragma unroll
        for (int j = 0; j < 4; ++j) {
            int c0 = n0 + j*8 + tig*2;
            float2 v1 = *(const float2*)&gV[(size_t)(bO + m1)*Dd + c0];
            float2 v2 = *(const float2*)&gV[(size_t)(bO + m2)*Dd + c0];
            float a0 = p1*v1.x, a1 = p1*v1.y, a2 = p2*v2.x, a3 = p2*v2.y;
            float h0,l0,h1,l1,h2,l2,h3,l3;
            split_bf(a0,h0,l0); split_bf(a1,h1,l1);
            split_bf(a2,h2,l2); split_bf(a3,h3,l3);
            *(unsigned*)(smA_hi + a2_off(m1, c0)) = pack_bf2(h0,h1);
            *(unsigned*)(smA_lo + a2_off(m1, c0)) = pack_bf2(l0,l1);
            *(unsigned*)(smA_hi + a2_off(m2, c0)) = pack_bf2(h2,h3);
            *(unsigned*)(smA_lo + a2_off(m2, c0)) = pack_bf2(l2,l3);
        }
    }
    __syncthreads();

    // ---------- attn = column sums of As ----------
    if (tid < 256) {
        float s = 0.f;
        #pragma unroll 4
        for (int m = 0; m < 96; ++m) {
            uint32_t o = a2_off(m, tid);
            float hv = __bfloat162float(*(const __nv_bfloat16*)(smA_hi + o));
            float lv = __bfloat162float(*(const __nv_bfloat16*)(smA_lo + o));
            s += hv + lv;
        }
        out_attn[(bO + n)*Dd + tid] = s;
    }
    __syncthreads();

    // ---------- GEMM2: du_in = As @ Wdu ----------
    mma_gemm(1, sb, tid, C);

    // ---------- epilogue 2: din = (C + bdu)*keep -> fp32 plane (reuse A region) ----------
    float* din = (float*)(sm + A_HI);   // [96][256] fp32 = 96KB
    #pragma unroll
    for (int i = 0; i < 3; ++i) {
        int m1 = rowb + i*16 + g, m2 = m1 + 8;
        float k1 = mk[m1], k2 = mk[m2];
        #pragma unroll
        for (int j = 0; j < 4; ++j) {
            int c0 = n0 + j*8 + tig*2;
            float2 d1 = make_float2((C[i][j][0] + b2s[c0]) * k1, (C[i][j][1] + b2s[c0+1]) * k1);
            float2 d2 = make_float2((C[i][j][2] + b2s[c0]) * k2, (C[i][j][3] + b2s[c0+1]) * k2);
            *(float2*)&din[m1*Dd + c0] = d1;
            *(float2*)&din[m2*Dd + c0] = d2;
        }
    }
    __syncthreads();

    // ---------- du[comp][c] = sum_m din[m][c] * vec[m][comp] ----------
    if (tid < 256) {
        float a0 = 0.f, a1 = 0.f, a2 = 0.f;
        #pragma unroll 4
        for (int m = 0; m < 96; ++m) {
            float v = din[m*Dd + tid];
            a0 = fmaf(v, vecs[m*3+0], a0);
            a1 = fmaf(v, vecs[m*3+1], a1);
            a2 = fmaf(v, vecs[m*3+2], a2);
        }
        gDU[((bO + n)*3 + 0)*Dd + tid] = a0;
        gDU[((bO + n)*3 + 1)*Dd + tid] = a1;
        gDU[((bO + n)*3 + 2)*Dd + tid] = a2;
    }
}

// ================= K2: w = du @ Wdih (SIMT, cp.async double-buffered) ============
#define WSMEM_BYTES (12288 + 2*32768)
__global__ __launch_bounds__(256) void w_kernel(const float* __restrict__ Wdih)
{
    extern __shared__ float wsm[];
    float* dus  = wsm;                 // 12*256
    float* wch0 = wsm + 3072;          // 16*512
    float* wch1 = wch0 + 8192;
    uint32_t sbw = smem_u32(wsm);
    uint32_t a_wch0 = sbw + 3072*4;
    uint32_t a_wch1 = a_wch0 + 8192*4;

    int tid = threadIdx.x;
    int b  = blockIdx.x / 24;
    int ng = blockIdx.x % 24;
    int nbase = ng * 4;

    // prefetch ks=0
    {
        const char* gsrc = (const char*)Wdih;
        #pragma unroll
        for (int i = 0; i < 8; ++i) {
            int e = tid + 256*i;
            cp16(a_wch0 + e*16, gsrc + e*16);
        }
        CP_COMMIT();
    }

    size_t dbase = (size_t)(b*Nn + nbase) * 3 * Dd;
    #pragma unroll
    for (int i = 0; i < 12; ++i)
        dus[tid + 256*i] = gDU[dbase + tid + 256*i];

    float acc0[12], acc1[12];
    #pragma unroll
    for (int q = 0; q < 12; ++q) { acc0[q] = 0.f; acc1[q] = 0.f; }

    #pragma unroll 1
    for (int ks = 0; ks < 16; ++ks) {
        uint32_t a_next = (ks & 1) ? a_wch0 : a_wch1;
        const float* wchc = (ks & 1) ? wch1 : wch0;
        if (ks < 15) {
            const char* gsrc = (const char*)(Wdih + (size_t)(ks+1)*16*512);
            #pragma unroll
            for (int i = 0; i < 8; ++i) {
                int e = tid + 256*i;
                cp16(a_next + e*16, gsrc + e*16);
            }
            CP_COMMIT(); CP_WAIT1();
        } else {
            CP_WAIT0();
        }
        __syncthreads();
        #pragma unroll
        for (int kk = 0; kk < 16; ++kk) {
            float w0 = wchc[kk*512 + tid];
            float w1 = wchc[kk*512 + 256 + tid];
            #pragma unroll
            for (int q = 0; q < 12; ++q) {
                float xv = dus[q*256 + ks*16 + kk];
                acc0[q] = fmaf(xv, w0, acc0[q]);
                acc1[q] = fmaf(xv, w1, acc1[q]);
            }
        }
        __syncthreads();
    }
    #pragma unroll
    for (int q = 0; q < 12; ++q) {
        int ni = q / 3, c = q % 3;
        gWS[((b*Nn + nbase + ni)*3 + c)*Dd + tid] = acc0[q];
        gWT[((b*Nn + nbase + ni)*3 + c)*Dd + tid] = acc1[q];
    }
}

// ================= K3: ipe = silu(E @ Wea + bea) * (ws . wt) =================
__global__ __launch_bounds__(NTHREADS, 1) void ipe_kernel(
    const float* __restrict__ edge,
    const float* __restrict__ bea,
    float* __restrict__ out_ipe)
{
    extern __shared__ char smraw[];
    uint32_t sb0 = smem_u32(smraw);
    uint32_t alpad = (1024u - (sb0 & 1023u)) & 1023u;
    char* sm = smraw + alpad;
    uint32_t sb = sb0 + alpad;

    char* smA_hi = sm + A_HI;
    char* smA_lo = sm + A_LO;
    float* misc  = (float*)(sm + MISC);
    float* bs    = misc;            // 256
    float* wsr   = bs + 256;        // 3x256

    int tid = threadIdx.x;
    int lane = tid & 31;
    int w = tid >> 5;
    int wg = w >> 3;
    int g = lane >> 2, tig = lane & 3;
    int n0 = (w & 7) * 32;
    int rowb = wg * 48;
    int b = blockIdx.x / Nn;
    int n = blockIdx.x % Nn;
    int bO = b * Nn;

    if (tid < 256) {
        bs[tid] = bea[tid];
        size_t wbase = (size_t)(bO + n) * 3 * Dd;
        #pragma unroll
        for (int i = 0; i < 3; ++i) wsr[i*256 + tid] = gWS[wbase + i*256 + tid];
    }
    convert_A(edge + (size_t)(bO + n)*Nn*Dd, smA_hi, smA_lo, tid);
    __syncthreads();

    float C[3][4][4];
    mma_gemm(2, sb, tid, C);

    #pragma unroll
    for (int i = 0; i < 3; ++i) {
        int m1 = rowb + i*16 + g, m2 = m1 + 8;
        const float* wt1 = &gWT[(size_t)((bO + m1)*3)*Dd];
        const float* wt2 = &gWT[(size_t)((bO + m2)*3)*Dd];
        float* o1 = &out_ipe[((size_t)(bO + n)*Nn + m1)*Dd];
        float* o2 = &out_ipe[((size_t)(bO + n)*Nn + m2)*Dd];
        #pragma unroll
        for (int j = 0; j < 4; ++j) {
            int c0 = n0 + j*8 + tig*2;
            float2 w0 = *(const float2*)&wsr[0*256 + c0];
            float2 w1 = *(const float2*)&wsr[1*256 + c0];
            float2 w2 = *(const float2*)&wsr[2*256 + c0];
            float2 bb = *(const float2*)&bs[c0];
            float2 t10 = *(const float2*)(wt1 + c0);
            float2 t11 = *(const float2*)(wt1 + 256 + c0);
            float2 t12 = *(const float2*)(wt1 + 512 + c0);
            float2 t20 = *(const float2*)(wt2 + c0);
            float2 t21 = *(const float2*)(wt2 + 256 + c0);
            float2 t22 = *(const float2*)(wt2 + 512 + c0);
            float2 r1, r2;
            r1.x = fast_silu(C[i][j][0] + bb.x) * (w0.x*t10.x + w1.x*t11.x + w2.x*t12.x);
            r1.y = fast_silu(C[i][j][1] + bb.y) * (w0.y*t10.y + w1.y*t11.y + w2.y*t12.y);
            r2.x = fast_silu(C[i][j][2] + bb.x) * (w0.x*t20.x + w1.x*t21.x + w2.x*t22.x);
            r2.y = fast_silu(C[i][j][3] + bb.y) * (w0.y*t20.y + w1.y*t21.y + w2.y*t22.y);
            *(float2*)(o1 + c0) = r1;
            *(float2*)(o2 + c0) = r2;
        }
    }
}

// ================= launch =================
extern "C" void kernel_launch(void* const* d_in, const int* in_sizes, int n_in,
                              void* d_out, int out_size)
{
    const float* x    = (const float*)d_in[0];
    const float* vec  = (const float*)d_in[1];
    const float* dist = (const float*)d_in[2];
    const float* edge = (const float*)d_in[3];
    const unsigned char* mraw = (const unsigned char*)d_in[4];
    const float* Wq   = (const float*)d_in[5];
    const float* bq   = (const float*)d_in[6];
    const float* Wk   = (const float*)d_in[7];
    const float* bk   = (const float*)d_in[8];
    const float* Wv   = (const float*)d_in[9];
    const float* bv   = (const float*)d_in[10];
    const float* Wdk  = (const float*)d_in[11];
    const float* bdk  = (const float*)d_in[12];
    const float* Wdu  = (const float*)d_in[13];
    const float* bdu  = (const float*)d_in[14];
    const float* Wdih = (const float*)d_in[15];
    const float* Wea  = (const float*)d_in[16];
    const float* bea  = (const float*)d_in[17];

    float* out_attn = (float*)d_out;                    // (B,N,D)
    float* out_ipe  = out_attn + Bb*Nn*Dd;              // (B,N,N,D)

    cudaFuncSetAttribute(fused_kernel, cudaFuncAttributeMaxDynamicSharedMemorySize, SMEM_BYTES);
    cudaFuncSetAttribute(ipe_kernel,   cudaFuncAttributeMaxDynamicSharedMemorySize, SMEM_BYTES);
    cudaFuncSetAttribute(w_kernel,     cudaFuncAttributeMaxDynamicSharedMemorySize, WSMEM_BYTES);
    cudaFuncSetAttribute(qkv_kernel,   cudaFuncAttributeMaxDynamicSharedMemorySize, QKV_SMEM_BYTES);

    mask_detect_kernel<<<1, 1024>>>(mraw);
    mask_apply_kernel<<<72, 1024>>>(mraw);
    wconv_kernel<<<384, 256>>>(Wdk, Wdu, Wea);
    qkv_kernel<<<192, 256, QKV_SMEM_BYTES>>>(x, Wq, bq, Wk, bk, Wv, bv);
    fused_kernel<<<Bb*Nn, NTHREADS, SMEM_BYTES>>>(edge, dist, vec, bdk, bdu, out_attn);
    w_kernel<<<Bb*24, 256, WSMEM_BYTES>>>(Wdih);
    ipe_kernel<<<Bb*Nn, NTHREADS, SMEM_BYTES>>>(edge, bea, out_ipe);
}

// round 17
// speedup vs baseline: 3.9554x; 1.0046x over previous
#include <cuda_runtime.h>
#include <cuda_bf16.h>
#include <cstdint>

#define Bb 8
#define Nn 96
#define Dd 256
#define CUTOFF 5.0f
#define PI_F 3.14159265358979f

// ================= scratch (device globals; no allocation allowed) =============
__device__ float gQ[Bb*Nn*Dd];
__device__ float gK[Bb*Nn*Dd];
__device__ float gV[Bb*Nn*Dd];
__device__ float gDU[Bb*Nn*3*Dd];
__device__ float gWS[Bb*Nn*3*Dd];
__device__ float gWT[Bb*Nn*3*Dd];
__device__ unsigned char gMask[Bb*Nn*Nn];
__device__ int gMode;
// Pre-converted weights: [mat: dk,du,ea][k-slice 0..7][32KB tile]
// Slice: [256 n][128B row: hi k0..31 in bytes 0..63 | lo k0..31 in bytes 64..127],
// 8-row atoms, XOR-swizzled (ldmatrix .col operand).
__device__ __align__(16) unsigned char gWB[3][8][32768];

// ================= helpers =================
__device__ __forceinline__ uint32_t smem_u32(const void* p) {
    uint32_t a;
    asm("{ .reg .u64 t; cvta.to.shared.u64 t, %1; cvt.u32.u64 %0, t; }" : "=r"(a) : "l"(p));
    return a;
}
__device__ __forceinline__ uint32_t swz(uint32_t b) { return b ^ ((b >> 3) & 0x70); }

// B slice byte offset: [256 n][32 k] bf16 + lo half, 128B rows, 8-row atoms
__device__ __forceinline__ uint32_t boff32(int n, int k, int lo) {
    uint32_t byte = ((n >> 3) << 10) + ((n & 7) << 7) + (lo << 6) + (k << 1);
    return swz(byte);
}
// A tile byte offset: [96 rows][256 cols] bf16, atoms 8r x 64c, 12 atom-rows per atom-col
__device__ __forceinline__ uint32_t a2_off(int row, int col) {
    uint32_t byte = (uint32_t)(((col >> 6) * 12 + (row >> 3)) << 10) + ((row & 7) << 7) + ((col & 63) << 1);
    return swz(byte);
}

__device__ __forceinline__ unsigned pack_bf2(float a, float b) {
    __nv_bfloat162 h = __floats2bfloat162_rn(a, b);
    return *reinterpret_cast<unsigned*>(&h);
}
__device__ __forceinline__ void split_bf(float x, float& hi, float& lo) {
    __nv_bfloat16 h = __float2bfloat16_rn(x);
    hi = __bfloat162float(h);
    lo = x - hi;
}

__device__ __forceinline__ void ldsm_x4(uint32_t& r0, uint32_t& r1, uint32_t& r2, uint32_t& r3, uint32_t addr) {
    asm volatile("ldmatrix.sync.aligned.m8n8.x4.shared.b16 {%0,%1,%2,%3}, [%4];"
                 : "=r"(r0), "=r"(r1), "=r"(r2), "=r"(r3) : "r"(addr));
}
__device__ __forceinline__ void mma16816(float* c, uint32_t a0, uint32_t a1, uint32_t a2, uint32_t a3,
                                         uint32_t b0, uint32_t b1) {
    asm volatile("mma.sync.aligned.m16n8k16.row.col.f32.bf16.bf16.f32 "
                 "{%0,%1,%2,%3}, {%4,%5,%6,%7}, {%8,%9}, {%0,%1,%2,%3};"
                 : "+f"(c[0]), "+f"(c[1]), "+f"(c[2]), "+f"(c[3])
                 : "r"(a0), "r"(a1), "r"(a2), "r"(a3), "r"(b0), "r"(b1));
}
__device__ __forceinline__ void cp16(uint32_t smem_addr, const void* gptr) {
    asm volatile("cp.async.cg.shared.global [%0], [%1], 16;" :: "r"(smem_addr), "l"(gptr));
}
#define CP_COMMIT() asm volatile("cp.async.commit_group;" ::: "memory")
#define CP_WAIT0()  asm volatile("cp.async.wait_group 0;" ::: "memory")
#define CP_WAIT1()  asm volatile("cp.async.wait_group 1;" ::: "memory")

// ================= FMA-only silu =================
__device__ __forceinline__ float fast_silu(float x) {
    float t = x * -1.4426950408889634f;
    t = fminf(fmaxf(t, -30.0f), 30.0f);
    float fn = rintf(t);
    float f  = t - fn;
    float p = 1.3333558e-3f;
    p = fmaf(p, f, 9.6181291e-3f);
    p = fmaf(p, f, 5.5504109e-2f);
    p = fmaf(p, f, 2.4022651e-1f);
    p = fmaf(p, f, 6.9314718e-1f);
    p = fmaf(p, f, 1.0f);
    float sc = __int_as_float(((int)fn + 127) << 23);
    float e = p * sc;
    float d = 1.0f + e;
    float y = __int_as_float(0x7EF311C3u - __float_as_int(d));
    y = y * (2.0f - d * y);
    y = y * (2.0f - d * y);
    y = y * (2.0f - d * y);
    return x * y;
}

// ================= mask dtype detect + apply (parallel) =================
__global__ void mask_detect_kernel(const unsigned char* __restrict__ raw) {
    __shared__ int ms;
    int tid = threadIdx.x;
    if (tid == 0) ms = 0;
    __syncthreads();
    int local = 0;
    const int NEL = Bb*Nn*Nn;
    for (int i = tid; i < NEL; i += 1024) {
        unsigned char bch = raw[i];
        if (bch != 0 && (i & 3) != 0) {
            if (bch == 0x80 || bch == 0x3F) local |= 2;
            else                            local |= 1;
        }
    }
    if (local) atomicOr(&ms, local);
    __syncthreads();
    if (tid == 0) gMode = ms;
}
__global__ void mask_apply_kernel(const unsigned char* __restrict__ raw) {
    int mode = gMode;
    int i = blockIdx.x * 1024 + threadIdx.x;   // 72*1024 == 73728 exactly
    unsigned char v;
    if (mode & 1)      v = (raw[i] != 0);
    else if (mode & 2) v = (((const float*)raw)[i] != 0.0f);
    else               v = (((const int*)raw)[i]   != 0);
    gMask[i] = v;
}

// ================= W pre-convert: W[k][n] fp32 -> interleaved hi|lo slices ====
__global__ __launch_bounds__(256) void wconv_kernel(
    const float* __restrict__ Wdk, const float* __restrict__ Wdu, const float* __restrict__ Wea)
{
    int idx = blockIdx.x * 256 + threadIdx.x;      // 3*256*128
    int mat = idx / (256*128);
    int rem = idx % (256*128);
    int n   = rem / 128;
    int kp  = rem % 128;
    int k0  = kp * 2;
    const float* W = (mat == 0) ? Wdk : (mat == 1) ? Wdu : Wea;
    float w0 = W[k0*Dd + n];
    float w1 = W[(k0+1)*Dd + n];
    float h0, l0, h1, l1;
    split_bf(w0, h0, l0);
    split_bf(w1, h1, l1);
    int slice = k0 >> 5;
    int kk = k0 & 31;
    *(unsigned*)(&gWB[mat][slice][boff32(n, kk, 0)]) = pack_bf2(h0, h1);
    *(unsigned*)(&gWB[mat][slice][boff32(n, kk, 1)]) = pack_bf2(l0, l1);
}

// ================= K0: Q/K/V = x @ W + b (cp.async pipelined, 192 blocks) =========
#define QKV_SMEM_BYTES (12288 + 2*32768)
__global__ __launch_bounds__(256) void qkv_kernel(
    const float* __restrict__ x,
    const float* __restrict__ Wq, const float* __restrict__ bq,
    const float* __restrict__ Wk, const float* __restrict__ bk,
    const float* __restrict__ Wv, const float* __restrict__ bv)
{
    extern __shared__ float qsm[];
    float* xs   = qsm;                 // 12*256
    float* wch0 = qsm + 3072;          // 32*256
    float* wch1 = wch0 + 8192;
    uint32_t sbq = smem_u32(qsm);
    uint32_t a_wch0 = sbq + 3072*4;
    uint32_t a_wch1 = a_wch0 + 8192*4;

    int tid  = threadIdx.x;
    int blk  = blockIdx.x;
    int wsel = blk % 3;
    int rg   = (blk / 3) & 7;
    int b    = blk / 24;
    int row0 = rg * 12;

    const float* W    = (wsel == 0) ? Wq : (wsel == 1) ? Wk : Wv;
    const float* bias = (wsel == 0) ? bq : (wsel == 1) ? bk : bv;
    float* out        = (wsel == 0) ? gQ : (wsel == 1) ? gK : gV;

    // prefetch chunk 0
    {
        const char* gsrc = (const char*)W;
        #pragma unroll
        for (int i = 0; i < 8; ++i) {
            int e = tid + 256*i;       // 2048 x 16B = 32KB
            cp16(a_wch0 + e*16, gsrc + e*16);
        }
        CP_COMMIT();
    }

    #pragma unroll
    for (int i = 0; i < 12; ++i)
        xs[i*256 + tid] = x[(b*Nn + row0 + i)*Dd + tid];

    float acc[12];
    #pragma unroll
    for (int i = 0; i < 12; ++i) acc[i] = 0.f;

    #pragma unroll 1
    for (int ks = 0; ks < 8; ++ks) {
        uint32_t a_next = (ks & 1) ? a_wch0 : a_wch1;
        const float* wchc = (ks & 1) ? wch1 : wch0;
        if (ks < 7) {
            const char* gsrc = (const char*)(W + (size_t)(ks+1)*32*Dd);
            #pragma unroll
            for (int i = 0; i < 8; ++i) {
                int e = tid + 256*i;
                cp16(a_next + e*16, gsrc + e*16);
            }
            CP_COMMIT(); CP_WAIT1();
        } else {
            CP_WAIT0();
        }
        __syncthreads();
        #pragma unroll
        for (int kk = 0; kk < 32; kk += 4) {
            float w0 = wchc[(kk+0)*256 + tid], w1 = wchc[(kk+1)*256 + tid];
            float w2 = wchc[(kk+2)*256 + tid], w3 = wchc[(kk+3)*256 + tid];
            #pragma unroll
            for (int r = 0; r < 12; ++r) {
                float4 xv = *(const float4*)&xs[r*256 + ks*32 + kk];
                acc[r] = fmaf(xv.x, w0, acc[r]);
                acc[r] = fmaf(xv.y, w1, acc[r]);
                acc[r] = fmaf(xv.z, w2, acc[r]);
                acc[r] = fmaf(xv.w, w3, acc[r]);
            }
        }
        __syncthreads();
    }
    float bb = bias[tid];
    #pragma unroll
    for (int r = 0; r < 12; ++r)
        out[(b*Nn + row0 + r)*Dd + tid] = acc[r] + bb;
}

// ================= smem layout (byte offsets after 1KB align) ======
#define A_HI 0
#define A_LO 49152
#define B0   98304
#define B1   131072
#define MISC 163840
#define SMEM_BYTES (1024 + 163840 + 8192)
#define NTHREADS 512

// convert 96x256 fp32 (global) -> A hi/lo bf16 swizzled tiles
__device__ __forceinline__ void convert_A(const float* __restrict__ src, char* smA_hi, char* smA_lo, int tid) {
    for (int idx = tid; idx < 96*32; idx += NTHREADS) {
        int row = idx >> 5;
        int c0  = (idx & 31) * 8;
        float4 e0 = *(const float4*)(src + row*Dd + c0);
        float4 e1 = *(const float4*)(src + row*Dd + c0 + 4);
        float h0,l0,h1,l1,h2,l2,h3,l3,h4,l4,h5,l5,h6,l6,h7,l7;
        split_bf(e0.x,h0,l0); split_bf(e0.y,h1,l1); split_bf(e0.z,h2,l2); split_bf(e0.w,h3,l3);
        split_bf(e1.x,h4,l4); split_bf(e1.y,h5,l5); split_bf(e1.z,h6,l6); split_bf(e1.w,h7,l7);
        uint32_t o = a2_off(row, c0);
        *(uint4*)(smA_hi + o) = make_uint4(pack_bf2(h0,h1), pack_bf2(h2,h3), pack_bf2(h4,h5), pack_bf2(h6,h7));
        *(uint4*)(smA_lo + o) = make_uint4(pack_bf2(l0,l1), pack_bf2(l2,l3), pack_bf2(l4,l5), pack_bf2(l6,l7));
    }
}

// async-stage one 32KB pre-swizzled B slice (hi|lo interleaved)
__device__ __forceinline__ void cp_slice(uint32_t smem_dst, const unsigned char* gsrc, int tid) {
    #pragma unroll
    for (int i = 0; i < 4; ++i) {
        int e = tid + NTHREADS*i;      // 2048 x 16B = 32KB
        cp16(smem_dst + e*16, gsrc + e*16);
    }
}

// one full 96x256x256 GEMM via HMMA, 3-term bf16 split.
// Term-major MMA issue within each i: dependent MMAs on the same accumulator are
// separated by 4 independent issues (j-loop), hiding HMMA accumulator RAW latency.
// Accumulation order per C[i][j] is unchanged (hh -> lh -> hl): bit-identical results.
__device__ __forceinline__ void mma_gemm(int mat, uint32_t sb, int tid, float C[3][4][4]) {
    int lane = tid & 31;
    int w = tid >> 5;
    int wg = w >> 3;
    int n0 = (w & 7) * 32;
    int rowb = wg * 48;
    int aRow = (lane & 7) + 8 * ((lane >> 3) & 1);
    int aK   = 8 * (lane >> 4);
    int bMat = lane >> 3;
    int bRow = lane & 7;
    int bNo  = (bMat >> 1) * 8;
    int bKo  = (bMat & 1) * 8;

    #pragma unroll
    for (int i = 0; i < 3; ++i)
        #pragma unroll
        for (int j = 0; j < 4; ++j)
            #pragma unroll
            for (int q = 0; q < 4; ++q) C[i][j][q] = 0.f;

    // prologue: slice 0 -> B0
    cp_slice(sb + B0, gWB[mat][0], tid);
    CP_COMMIT();

    #pragma unroll 1
    for (int s = 0; s < 8; ++s) {
        uint32_t bufc = (s & 1) ? (sb + B1) : (sb + B0);
        uint32_t bufn = (s & 1) ? (sb + B0) : (sb + B1);
        if (s < 7) { cp_slice(bufn, gWB[mat][s+1], tid); CP_COMMIT(); CP_WAIT1(); }
        else       { CP_WAIT0(); }
        __syncthreads();

        #pragma unroll
        for (int t = 0; t < 2; ++t) {
            int k0 = t * 16;
            uint32_t bh[4][2], bl[4][2];
            #pragma unroll
            for (int jp = 0; jp < 2; ++jp) {
                int rn = n0 + jp*16 + bNo + bRow;
                ldsm_x4(bh[jp*2][0], bh[jp*2][1], bh[jp*2+1][0], bh[jp*2+1][1],
                        bufc + boff32(rn, k0 + bKo, 0));
                ldsm_x4(bl[jp*2][0], bl[jp*2][1], bl[jp*2+1][0], bl[jp*2+1][1],
                        bufc + boff32(rn, k0 + bKo, 1));
            }
            #pragma unroll
            for (int i = 0; i < 3; ++i) {
                uint32_t ao = a2_off(rowb + i*16 + aRow, s*32 + k0 + aK);
                uint32_t ah0,ah1,ah2,ah3, al0,al1,al2,al3;
                ldsm_x4(ah0,ah1,ah2,ah3, sb + A_HI + ao);
                ldsm_x4(al0,al1,al2,al3, sb + A_LO + ao);
                // term-major: 4 independent MMAs between dependent pairs
                #pragma unroll
                for (int j = 0; j < 4; ++j)
                    mma16816(C[i][j], ah0,ah1,ah2,ah3, bh[j][0], bh[j][1]);
                #pragma unroll
                for (int j = 0; j < 4; ++j)
                    mma16816(C[i][j], al0,al1,al2,al3, bh[j][0], bh[j][1]);
                #pragma unroll
                for (int j = 0; j < 4; ++j)
                    mma16816(C[i][j], ah0,ah1,ah2,ah3, bl[j][0], bl[j][1]);
            }
        }
        __syncthreads();
    }
}

// ================= K1: fused dk-GEMM + attention + du-GEMM =================
__global__ __launch_bounds__(NTHREADS, 1) void fused_kernel(
    const float* __restrict__ edge,
    const float* __restrict__ dist,
    const float* __restrict__ vec,
    const float* __restrict__ bdk, const float* __restrict__ bdu,
    float* __restrict__ out_attn)
{
    extern __shared__ char smraw[];
    uint32_t sb0 = smem_u32(smraw);
    uint32_t alpad = (1024u - (sb0 & 1023u)) & 1023u;
    char* sm = smraw + alpad;
    uint32_t sb = sb0 + alpad;

    char* smA_hi = sm + A_HI;
    char* smA_lo = sm + A_LO;
    float* misc  = (float*)(sm + MISC);
    float* qs    = misc;            // 256
    float* b1s   = qs + 256;        // bdk
    float* b2s   = b1s + 256;       // bdu
    float* scl   = b2s + 256;       // 96
    float* mk    = scl + 96;        // 96
    float* vecs  = mk + 96;         // 288
    float* scr   = vecs + 288;      // 768 scratch (reduction partials)

    int tid = threadIdx.x;
    int lane = tid & 31;
    int w = tid >> 5;
    int wg = w >> 3;
    int g = lane >> 2, tig = lane & 3;
    int n0 = (w & 7) * 32;
    int rowb = wg * 48;
    int b = blockIdx.x / Nn;
    int n = blockIdx.x % Nn;
    int bO = b * Nn;

    if (tid < 256) {
        qs[tid]  = gQ[(bO + n)*Dd + tid];
        b1s[tid] = bdk[tid];
        b2s[tid] = bdu[tid];
    }
    if (tid < 96) {
        unsigned char mm = gMask[(bO + n)*Nn + tid];
        float dd = dist[(bO + n)*Nn + tid];
        float cs = (dd < CUTOFF) ? 0.5f*(cosf(dd*(PI_F/CUTOFF)) + 1.f) : 0.f;
        scl[tid] = mm ? 0.f : cs;
        mk[tid]  = mm ? 0.f : 1.f;
    }
    if (tid < 288) vecs[tid] = vec[(size_t)(bO + n)*Nn*3 + tid];

    convert_A(edge + (size_t)(bO + n)*Nn*Dd, smA_hi, smA_lo, tid);
    __syncthreads();

    float C[3][4][4];

    // ---------- GEMM1: dk preact ----------
    mma_gemm(0, sb, tid, C);

    // ---------- epilogue 1: silu + attn weights + probs + As ----------
    #pragma unroll
    for (int i = 0; i < 3; ++i) {
        int m1 = rowb + i*16 + g, m2 = m1 + 8;
        float t1 = 0.f, t2 = 0.f;
        #pragma unroll
        for (int j = 0; j < 4; ++j) {
            int c0 = n0 + j*8 + tig*2;
            float bb0 = b1s[c0], bb1 = b1s[c0+1];
            float q0 = qs[c0], q1 = qs[c0+1];
            float d0 = fast_silu(C[i][j][0] + bb0);
            float d1 = fast_silu(C[i][j][1] + bb1);
            float d2 = fast_silu(C[i][j][2] + bb0);
            float d3 = fast_silu(C[i][j][3] + bb1);
            float2 k1v = *(const float2*)&gK[(size_t)(bO + m1)*Dd + c0];
            float2 k2v = *(const float2*)&gK[(size_t)(bO + m2)*Dd + c0];
            t1 = fmaf(d0, q0*k1v.x, fmaf(d1, q1*k1v.y, t1));
            t2 = fmaf(d2, q0*k2v.x, fmaf(d3, q1*k2v.y, t2));
        }
        t1 += __shfl_xor_sync(0xffffffffu, t1, 1);
        t1 += __shfl_xor_sync(0xffffffffu, t1, 2);
        t2 += __shfl_xor_sync(0xffffffffu, t2, 1);
        t2 += __shfl_xor_sync(0xffffffffu, t2, 2);
        float p1 = fast_silu(t1) * scl[m1];
        float p2 = fast_silu(t2) * scl[m2];
        #pragma unroll
        for (int j = 0; j < 4; ++j) {
            int c0 = n0 + j*8 + tig*2;
            float2 v1 = *(const float2*)&gV[(size_t)(bO + m1)*Dd + c0];
            float2 v2 = *(const float2*)&gV[(size_t)(bO + m2)*Dd + c0];
            float a0 = p1*v1.x, a1 = p1*v1.y, a2 = p2*v2.x, a3 = p2*v2.y;
            float h0,l0,h1,l1,h2,l2,h3,l3;
            split_bf(a0,h0,l0); split_bf(a1,h1,l1);
            split_bf(a2,h2,l2); split_bf(a3,h3,l3);
            *(unsigned*)(smA_hi + a2_off(m1, c0)) = pack_bf2(h0,h1);
            *(unsigned*)(smA_lo + a2_off(m1, c0)) = pack_bf2(l0,l1);
            *(unsigned*)(smA_hi + a2_off(m2, c0)) = pack_bf2(h2,h3);
            *(unsigned*)(smA_lo + a2_off(m2, c0)) = pack_bf2(l2,l3);
        }
    }
    __syncthreads();

    // ---------- attn = column sums of As (both thread-halves, combine) ----------
    {
        int c = tid & 255;
        int half = tid >> 8;
        float s = 0.f;
        int m0 = half * 48;
        #pragma unroll 4
        for (int m = m0; m < m0 + 48; ++m) {
            uint32_t o = a2_off(m, c);
            float hv = __bfloat162float(*(const __nv_bfloat16*)(smA_hi + o));
            float lv = __bfloat162float(*(const __nv_bfloat16*)(smA_lo + o));
            s += hv + lv;
        }
        if (half) scr[c] = s;
        __syncthreads();
        if (!half) out_attn[(bO + n)*Dd + c] = s + scr[c];
    }
    __syncthreads();

    // ---------- GEMM2: du_in = As @ Wdu ----------
    mma_gemm(1, sb, tid, C);

    // ---------- epilogue 2: din = (C + bdu)*keep -> fp32 plane (reuse A region) ----------
    float* din = (float*)(sm + A_HI);   // [96][256] fp32 = 96KB
    #pragma unroll
    for (int i = 0; i < 3; ++i) {
        int m1 = rowb + i*16 + g, m2 = m1 + 8;
        float k1 = mk[m1], k2 = mk[m2];
        #pragma unroll
        for (int j = 0; j < 4; ++j) {
            int c0 = n0 + j*8 + tig*2;
            float2 d1 = make_float2((C[i][j][0] + b2s[c0]) * k1, (C[i][j][1] + b2s[c0+1]) * k1);
            float2 d2 = make_float2((C[i][j][2] + b2s[c0]) * k2, (C[i][j][3] + b2s[c0+1]) * k2);
            *(float2*)&din[m1*Dd + c0] = d1;
            *(float2*)&din[m2*Dd + c0] = d2;
        }
    }
    __syncthreads();

    // ---------- du[comp][c] = sum_m din[m][c] * vec[m][comp] (split + combine) ----------
    {
        int c = tid & 255;
        int half = tid >> 8;
        float a0 = 0.f, a1 = 0.f, a2 = 0.f;
        int m0 = half * 48;
        #pragma unroll 4
        for (int m = m0; m < m0 + 48; ++m) {
            float v = din[m*Dd + c];
            a0 = fmaf(v, vecs[m*3+0], a0);
            a1 = fmaf(v, vecs[m*3+1], a1);
            a2 = fmaf(v, vecs[m*3+2], a2);
        }
        if (half) { scr[c] = a0; scr[256 + c] = a1; scr[512 + c] = a2; }
        __syncthreads();
        if (!half) {
            gDU[((bO + n)*3 + 0)*Dd + c] = a0 + scr[c];
            gDU[((bO + n)*3 + 1)*Dd + c] = a1 + scr[256 + c];
            gDU[((bO + n)*3 + 2)*Dd + c] = a2 + scr[512 + c];
        }
    }
}

// ================= K2: w = du @ Wdih (SIMT, cp.async double-buffered) ============
#define WSMEM_BYTES (12288 + 2*32768)
__global__ __launch_bounds__(256) void w_kernel(const float* __restrict__ Wdih)
{
    extern __shared__ float wsm[];
    float* dus  = wsm;                 // 12*256
    float* wch0 = wsm + 3072;          // 16*512
    float* wch1 = wch0 + 8192;
    uint32_t sbw = smem_u32(wsm);
    uint32_t a_wch0 = sbw + 3072*4;
    uint32_t a_wch1 = a_wch0 + 8192*4;

    int tid = threadIdx.x;
    int b  = blockIdx.x / 24;
    int ng = blockIdx.x % 24;
    int nbase = ng * 4;

    // prefetch ks=0
    {
        const char* gsrc = (const char*)Wdih;
        #pragma unroll
        for (int i = 0; i < 8; ++i) {
            int e = tid + 256*i;
            cp16(a_wch0 + e*16, gsrc + e*16);
        }
        CP_COMMIT();
    }

    size_t dbase = (size_t)(b*Nn + nbase) * 3 * Dd;
    #pragma unroll
    for (int i = 0; i < 12; ++i)
        dus[tid + 256*i] = gDU[dbase + tid + 256*i];

    float acc0[12], acc1[12];
    #pragma unroll
    for (int q = 0; q < 12; ++q) { acc0[q] = 0.f; acc1[q] = 0.f; }

    #pragma unroll 1
    for (int ks = 0; ks < 16; ++ks) {
        uint32_t a_next = (ks & 1) ? a_wch0 : a_wch1;
        const float* wchc = (ks & 1) ? wch1 : wch0;
        if (ks < 15) {
            const char* gsrc = (const char*)(Wdih + (size_t)(ks+1)*16*512);
            #pragma unroll
            for (int i = 0; i < 8; ++i) {
                int e = tid + 256*i;
                cp16(a_next + e*16, gsrc + e*16);
            }
            CP_COMMIT(); CP_WAIT1();
        } else {
            CP_WAIT0();
        }
        __syncthreads();
        #pragma unroll
        for (int kk = 0; kk < 16; ++kk) {
            float w0 = wchc[kk*512 + tid];
            float w1 = wchc[kk*512 + 256 + tid];
            #pragma unroll
            for (int q = 0; q < 12; ++q) {
                float xv = dus[q*256 + ks*16 + kk];
                acc0[q] = fmaf(xv, w0, acc0[q]);
                acc1[q] = fmaf(xv, w1, acc1[q]);
            }
        }
        __syncthreads();
    }
    #pragma unroll
    for (int q = 0; q < 12; ++q) {
        int ni = q / 3, c = q % 3;
        gWS[((b*Nn + nbase + ni)*3 + c)*Dd + tid] = acc0[q];
        gWT[((b*Nn + nbase + ni)*3 + c)*Dd + tid] = acc1[q];
    }
}

// ================= K3: ipe = silu(E @ Wea + bea) * (ws . wt) =================
__global__ __launch_bounds__(NTHREADS, 1) void ipe_kernel(
    const float* __restrict__ edge,
    const float* __restrict__ bea,
    float* __restrict__ out_ipe)
{
    extern __shared__ char smraw[];
    uint32_t sb0 = smem_u32(smraw);
    uint32_t alpad = (1024u - (sb0 & 1023u)) & 1023u;
    char* sm = smraw + alpad;
    uint32_t sb = sb0 + alpad;

    char* smA_hi = sm + A_HI;
    char* smA_lo = sm + A_LO;
    float* misc  = (float*)(sm + MISC);
    float* bs    = misc;            // 256
    float* wsr   = bs + 256;        // 3x256

    int tid = threadIdx.x;
    int lane = tid & 31;
    int w = tid >> 5;
    int wg = w >> 3;
    int g = lane >> 2, tig = lane & 3;
    int n0 = (w & 7) * 32;
    int rowb = wg * 48;
    int b = blockIdx.x / Nn;
    int n = blockIdx.x % Nn;
    int bO = b * Nn;

    if (tid < 256) {
        bs[tid] = bea[tid];
        size_t wbase = (size_t)(bO + n) * 3 * Dd;
        #pragma unroll
        for (int i = 0; i < 3; ++i) wsr[i*256 + tid] = gWS[wbase + i*256 + tid];
    }
    convert_A(edge + (size_t)(bO + n)*Nn*Dd, smA_hi, smA_lo, tid);
    __syncthreads();

    float C[3][4][4];
    mma_gemm(2, sb, tid, C);

    #pragma unroll
    for (int i = 0; i < 3; ++i) {
        int m1 = rowb + i*16 + g, m2 = m1 + 8;
        const float* wt1 = &gWT[(size_t)((bO + m1)*3)*Dd];
        const float* wt2 = &gWT[(size_t)((bO + m2)*3)*Dd];
        float* o1 = &out_ipe[((size_t)(bO + n)*Nn + m1)*Dd];
        float* o2 = &out_ipe[((size_t)(bO + n)*Nn + m2)*Dd];
        #pragma unroll
        for (int j = 0; j < 4; ++j) {
            int c0 = n0 + j*8 + tig*2;
            float2 w0 = *(const float2*)&wsr[0*256 + c0];
            float2 w1 = *(const float2*)&wsr[1*256 + c0];
            float2 w2 = *(const float2*)&wsr[2*256 + c0];
            float2 bb = *(const float2*)&bs[c0];
            float2 t10 = *(const float2*)(wt1 + c0);
            float2 t11 = *(const float2*)(wt1 + 256 + c0);
            float2 t12 = *(const float2*)(wt1 + 512 + c0);
            float2 t20 = *(const float2*)(wt2 + c0);
            float2 t21 = *(const float2*)(wt2 + 256 + c0);
            float2 t22 = *(const float2*)(wt2 + 512 + c0);
            float2 r1, r2;
            r1.x = fast_silu(C[i][j][0] + bb.x) * (w0.x*t10.x + w1.x*t11.x + w2.x*t12.x);
            r1.y = fast_silu(C[i][j][1] + bb.y) * (w0.y*t10.y + w1.y*t11.y + w2.y*t12.y);
            r2.x = fast_silu(C[i][j][2] + bb.x) * (w0.x*t20.x + w1.x*t21.x + w2.x*t22.x);
            r2.y = fast_silu(C[i][j][3] + bb.y) * (w0.y*t20.y + w1.y*t21.y + w2.y*t22.y);
            *(float2*)(o1 + c0) = r1;
            *(float2*)(o2 + c0) = r2;
        }
    }
}

// ================= launch =================
extern "C" void kernel_launch(void* const* d_in, const int* in_sizes, int n_in,
                              void* d_out, int out_size)
{
    const float* x    = (const float*)d_in[0];
    const float* vec  = (const float*)d_in[1];
    const float* dist = (const float*)d_in[2];
    const float* edge = (const float*)d_in[3];
    const unsigned char* mraw = (const unsigned char*)d_in[4];
    const float* Wq   = (const float*)d_in[5];
    const float* bq   = (const float*)d_in[6];
    const float* Wk   = (const float*)d_in[7];
    const float* bk   = (const float*)d_in[8];
    const float* Wv   = (const float*)d_in[9];
    const float* bv   = (const float*)d_in[10];
    const float* Wdk  = (const float*)d_in[11];
    const float* bdk  = (const float*)d_in[12];
    const float* Wdu  = (const float*)d_in[13];
    const float* bdu  = (const float*)d_in[14];
    const float* Wdih = (const float*)d_in[15];
    const float* Wea  = (const float*)d_in[16];
    const float* bea  = (const float*)d_in[17];

    float* out_attn = (float*)d_out;                    // (B,N,D)
    float* out_ipe  = out_attn + Bb*Nn*Dd;              // (B,N,N,D)

    cudaFuncSetAttribute(fused_kernel, cudaFuncAttributeMaxDynamicSharedMemorySize, SMEM_BYTES);
    cudaFuncSetAttribute(ipe_kernel,   cudaFuncAttributeMaxDynamicSharedMemorySize, SMEM_BYTES);
    cudaFuncSetAttribute(w_kernel,     cudaFuncAttributeMaxDynamicSharedMemorySize, WSMEM_BYTES);
    cudaFuncSetAttribute(qkv_kernel,   cudaFuncAttributeMaxDynamicSharedMemorySize, QKV_SMEM_BYTES);

    mask_detect_kernel<<<1, 1024>>>(mraw);
    mask_apply_kernel<<<72, 1024>>>(mraw);
    wconv_kernel<<<384, 256>>>(Wdk, Wdu, Wea);
    qkv_kernel<<<192, 256, QKV_SMEM_BYTES>>>(x, Wq, bq, Wk, bk, Wv, bv);
    fused_kernel<<<Bb*Nn, NTHREADS, SMEM_BYTES>>>(edge, dist, vec, bdk, bdu, out_attn);
    w_kernel<<<Bb*24, 256, WSMEM_BYTES>>>(Wdih);
    ipe_kernel<<<Bb*Nn, NTHREADS, SMEM_BYTES>>>(edge, bea, out_ipe);
}